// round 11
// baseline (speedup 1.0000x reference)
#include <cuda_runtime.h>
#include <cuda_fp16.h>
#include <mma.h>

using namespace nvcuda;

#define NN  25000
#define NE  400000
#define NEF 425000   /* NE + NN self-loops */
#define D   128
#define NH  4
#define EFD 32
#define NL  6

/* ---------------- scratch (static device globals; no allocs) -------------- */
__device__ __align__(16) float  g_h[NN * D];
__device__ __align__(16) float  g_hm[NN * D];
__device__ __align__(16) __half g_x[NN * NH * D];
__device__ __align__(16) float  g_als[NN * NH];
__device__ __align__(16) float  g_ald[NN * NH];
__device__ __align__(16) float  g_ale[NL * NE * NH];    /* all layers, edge order */
__device__ __align__(16) float  g_lg[NEF * NH];         /* CSR-order normalized weights */
__device__ int   g_rowptr[NN + 1];
__device__ int   g_counts[NN];
__device__ int   g_fill[NN];
__device__ int   g_csrsrc[NEF];
__device__ int   g_csreid[NEF];
__device__ __align__(16) float g_eamean[EFD];
__device__ __align__(16) float g_partial[256 * EFD];
__device__ __align__(16) float g_v[NL * NH * EFD];
__device__ __align__(16) float g_aleself[NL * NH];
__device__ __align__(16) float g_t[NN * D];
__device__ __align__(16) float g_u[NN * D];
__device__ int   g_bsums[32];

/* ---------------- helpers ---------------- */
__device__ __forceinline__ float wredsum(float v) {
    #pragma unroll
    for (int o = 16; o; o >>= 1) v += __shfl_xor_sync(0xffffffffu, v, o);
    return v;
}
__device__ __forceinline__ void wredsum4(float4& v) {
    #pragma unroll
    for (int o = 16; o; o >>= 1) {
        v.x += __shfl_xor_sync(0xffffffffu, v.x, o);
        v.y += __shfl_xor_sync(0xffffffffu, v.y, o);
        v.z += __shfl_xor_sync(0xffffffffu, v.z, o);
        v.w += __shfl_xor_sync(0xffffffffu, v.w, o);
    }
}
__device__ __forceinline__ void wredmax4(float4& v) {
    #pragma unroll
    for (int o = 16; o; o >>= 1) {
        v.x = fmaxf(v.x, __shfl_xor_sync(0xffffffffu, v.x, o));
        v.y = fmaxf(v.y, __shfl_xor_sync(0xffffffffu, v.y, o));
        v.z = fmaxf(v.z, __shfl_xor_sync(0xffffffffu, v.z, o));
        v.w = fmaxf(v.w, __shfl_xor_sync(0xffffffffu, v.w, o));
    }
}
__device__ __forceinline__ float sel4(const float4& v, int h) {
    return h == 0 ? v.x : h == 1 ? v.y : h == 2 ? v.z : v.w;
}

/* ---------------- edge-attr mean (deterministic 2-stage) ---------------- */
__global__ void k_eamean1(const float* __restrict__ ea) {
    const int SPAN = 1563;
    int blk = blockIdx.x;
    int w = threadIdx.x >> 5, lane = threadIdx.x & 31;
    long start = (long)blk * SPAN;
    long end = start + SPAN; if (end > NE) end = NE;
    float s = 0.f;
    for (long e = start + w; e < end; e += 4) s += ea[e * EFD + lane];
    __shared__ float sm[4][32];
    sm[w][lane] = s;
    __syncthreads();
    if (w == 0) {
        float t = sm[0][lane] + sm[1][lane] + sm[2][lane] + sm[3][lane];
        g_partial[blk * 32 + lane] = t;
    }
}
__global__ void k_eamean2() {
    int lane = threadIdx.x;
    float s = 0.f;
    for (int b = 0; b < 256; b++) s += g_partial[b * 32 + lane];
    g_eamean[lane] = s * (1.f / (float)NE);
}

/* ---------------- CSR build ---------------- */
__global__ void k_init_counts() {
    int i = blockIdx.x * blockDim.x + threadIdx.x;
    if (i < NN) g_counts[i] = 1;   /* self loop */
}
__global__ void k_count(const int* __restrict__ dst) {
    int e = blockIdx.x * blockDim.x + threadIdx.x;
    if (e < NE) atomicAdd(&g_counts[dst[e]], 1);
}
__global__ void k_scan_local() {
    __shared__ int sm[1024];
    int base = blockIdx.x * 1024;
    int t = threadIdx.x;
    int v = (base + t < NN) ? g_counts[base + t] : 0;
    sm[t] = v;
    __syncthreads();
    #pragma unroll
    for (int off = 1; off < 1024; off <<= 1) {
        int x = (t >= off) ? sm[t - off] : 0;
        __syncthreads();
        sm[t] += x;
        __syncthreads();
    }
    if (base + t < NN) g_rowptr[base + t] = sm[t] - v;   /* exclusive */
    if (t == 1023) g_bsums[blockIdx.x] = sm[1023];
}
__global__ void k_scan_fixup(int nb) {
    int lane = threadIdx.x;                 /* 32 threads; nb <= 32 */
    int v = (lane < nb) ? g_bsums[lane] : 0;
    int orig = v;
    #pragma unroll
    for (int off = 1; off < 32; off <<= 1) {
        int x = __shfl_up_sync(0xffffffffu, v, off);
        if (lane >= off) v += x;
    }
    if (lane < nb) g_bsums[lane] = v - orig;   /* exclusive */
    if (lane == 31) g_rowptr[NN] = v;          /* total */
}
__global__ void k_scan_add() {
    int i = blockIdx.x * blockDim.x + threadIdx.x;
    if (i < NN) {
        int r = g_rowptr[i] + g_bsums[i >> 10];
        g_rowptr[i] = r;
        g_fill[i] = r;
    }
}
__global__ void k_scatter_edges(const int* __restrict__ src, const int* __restrict__ dst) {
    int e = blockIdx.x * blockDim.x + threadIdx.x;
    if (e < NE) {
        int d = dst[e];
        int pos = atomicAdd(&g_fill[d], 1);
        g_csrsrc[pos] = src[e];
        g_csreid[pos] = e;
    }
}
__global__ void k_scatter_self() {
    int i = blockIdx.x * blockDim.x + threadIdx.x;
    if (i < NN) {
        int pos = atomicAdd(&g_fill[i], 1);
        g_csrsrc[pos] = i;
        g_csreid[pos] = NE + i;
    }
}

/* ================= tensor-core GEMM: C[M,N] = A[M,128] @ B[128,N] =========
   fp16 HMMA, fp32 accumulate. Optional fused attention dots (av/dv) for the
   N=512 x-projection GEMM. Optional dual-output mode (C2 != null): grid.x=2,
   blockIdx.x selects the [128,128] B slice and output buffer (head GEMMs).
   All shuffles warp-uniform. */

#define AS_H 5120      /* halves per A stage: 128*40 */
#define BS_H 4352      /* halves per B stage: 32*136 */
#define SMEM_BYTES 37888

__device__ __forceinline__ void cvt_sts(__half* dst, const float4* p) {
    __half2 h[8];
    h[0] = __floats2half2_rn(p[0].x, p[0].y);
    h[1] = __floats2half2_rn(p[0].z, p[0].w);
    h[2] = __floats2half2_rn(p[1].x, p[1].y);
    h[3] = __floats2half2_rn(p[1].z, p[1].w);
    h[4] = __floats2half2_rn(p[2].x, p[2].y);
    h[5] = __floats2half2_rn(p[2].z, p[2].w);
    h[6] = __floats2half2_rn(p[3].x, p[3].y);
    h[7] = __floats2half2_rn(p[3].z, p[3].w);
    *(uint4*)dst       = *(const uint4*)&h[0];
    *(uint4*)(dst + 8) = *(const uint4*)&h[4];
}

template <typename OutT>
__global__ void __launch_bounds__(256)
k_gemm_mma(const float* __restrict__ A, const float* __restrict__ B,
           OutT* __restrict__ C, int M, int N, const float* __restrict__ bias,
           const float* __restrict__ av, const float* __restrict__ dv,
           float* __restrict__ als_out, float* __restrict__ ald_out,
           OutT* __restrict__ C2) {
    __shared__ __align__(16) char smem[SMEM_BYTES];
    __half* As = (__half*)smem;                 /* [2][128][40] */
    __half* Bs = (__half*)(smem + 20480);       /* [2][32][136] */
    float*  Cs = (float*)smem;                  /* [128][72] epilogue reuse */

    const int tid = threadIdx.x;
    const int bm = blockIdx.y * 128;
    const int bn = C2 ? 0 : blockIdx.x * 128;
    if (C2 && blockIdx.x == 1) { B += 128 * 128; C = C2; }
    const int warp = tid >> 5;
    const int wm = warp >> 1;      /* 0..3 */
    const int wn = warp & 1;       /* 0..1 */

    const int r_a = tid >> 1, ca = (tid & 1) * 16;
    const int r_b = tid >> 3, cb = (tid & 7) * 16;
    const bool arow_ok = (bm + r_a) < M;
    const float* Aptr = A + (long)(bm + r_a) * 128 + ca;
    const float* Bptr = B + (long)r_b * N + bn + cb;

    float4 pa[4], pb[4];
    #define LOAD_A(kk) do { \
        if (arow_ok) { \
            pa[0] = *(const float4*)(Aptr + (kk)); \
            pa[1] = *(const float4*)(Aptr + (kk) + 4); \
            pa[2] = *(const float4*)(Aptr + (kk) + 8); \
            pa[3] = *(const float4*)(Aptr + (kk) + 12); \
        } else { pa[0] = pa[1] = pa[2] = pa[3] = make_float4(0.f,0.f,0.f,0.f); } \
    } while (0)
    #define LOAD_B(kk) do { \
        const float* bp = Bptr + (long)(kk) * N; \
        pb[0] = *(const float4*)bp; \
        pb[1] = *(const float4*)(bp + 4); \
        pb[2] = *(const float4*)(bp + 8); \
        pb[3] = *(const float4*)(bp + 12); \
    } while (0)
    #define STS(st) do { \
        cvt_sts(As + (st) * AS_H + r_a * 40 + ca, pa); \
        cvt_sts(Bs + (st) * BS_H + r_b * 136 + cb, pb); \
    } while (0)

    wmma::fragment<wmma::accumulator, 16, 16, 16, float> cf[2][4];
    #pragma unroll
    for (int i = 0; i < 2; i++)
        #pragma unroll
        for (int j = 0; j < 4; j++) wmma::fill_fragment(cf[i][j], 0.f);

    LOAD_A(0); LOAD_B(0);
    STS(0);
    __syncthreads();

    #pragma unroll
    for (int t = 0; t < 4; t++) {
        if (t < 3) { LOAD_A((t + 1) * 32); LOAD_B((t + 1) * 32); }
        const int st = t & 1;
        #pragma unroll
        for (int ks = 0; ks < 2; ks++) {
            wmma::fragment<wmma::matrix_a, 16, 16, 16, __half, wmma::row_major> af0, af1;
            wmma::load_matrix_sync(af0, As + st * AS_H + (wm * 32) * 40 + ks * 16, 40);
            wmma::load_matrix_sync(af1, As + st * AS_H + (wm * 32 + 16) * 40 + ks * 16, 40);
            #pragma unroll
            for (int j = 0; j < 4; j++) {
                wmma::fragment<wmma::matrix_b, 16, 16, 16, __half, wmma::row_major> bf;
                wmma::load_matrix_sync(bf, Bs + st * BS_H + (ks * 16) * 136 + wn * 64 + j * 16, 136);
                wmma::mma_sync(cf[0][j], af0, bf, cf[0][j]);
                wmma::mma_sync(cf[1][j], af1, bf, cf[1][j]);
            }
        }
        if (t < 3) {
            __syncthreads();
            STS((t + 1) & 1);
            __syncthreads();
        }
    }

    /* epilogue: two phases through smem (Cs reuses As/Bs) */
    const int r = tid >> 1;
    const int gm = bm + r;
    const int head = blockIdx.x;                     /* valid for N=512 x-GEMM */
    float ds = 0.f, dd = 0.f;

    #pragma unroll
    for (int ph = 0; ph < 2; ph++) {
        __syncthreads();
        #pragma unroll
        for (int i = 0; i < 2; i++)
            #pragma unroll
            for (int q = 0; q < 2; q++)
                wmma::store_matrix_sync(Cs + (wm * 32 + i * 16) * 72 + wn * 32 + q * 16,
                                        cf[i][ph * 2 + q], 72, wmma::mem_row_major);
        __syncthreads();
        int c0 = (tid & 1) * 32;
        if (gm < M) {
            const float* srow = Cs + r * 72 + c0;
            int colb = (c0 ? 64 : 0) + ph * 32;      /* column within 128 */
            int gnb = bn + colb;
            #pragma unroll
            for (int c = 0; c < 32; c += 4) {
                float4 v = *(const float4*)(srow + c);
                if (bias) {
                    v.x += bias[gnb + c + 0];
                    v.y += bias[gnb + c + 1];
                    v.z += bias[gnb + c + 2];
                    v.w += bias[gnb + c + 3];
                }
                if (av) {
                    float4 a4 = *(const float4*)(av + head * D + colb + c);
                    float4 b4 = *(const float4*)(dv + head * D + colb + c);
                    ds += v.x * a4.x + v.y * a4.y + v.z * a4.z + v.w * a4.w;
                    dd += v.x * b4.x + v.y * b4.y + v.z * b4.z + v.w * b4.w;
                }
                if (sizeof(OutT) == 4) {
                    *(float4*)((float*)C + (long)gm * N + gnb + c) = v;
                } else {
                    __half2 h0 = __floats2half2_rn(v.x, v.y);
                    __half2 h1 = __floats2half2_rn(v.z, v.w);
                    uint2 u; u.x = *(unsigned*)&h0; u.y = *(unsigned*)&h1;
                    *(uint2*)((__half*)C + (long)gm * N + gnb + c) = u;
                }
            }
        }
    }
    /* warp-uniform shuffle: executed by ALL lanes (av is uniform) */
    if (av) {
        ds += __shfl_xor_sync(0xffffffffu, ds, 1);
        dd += __shfl_xor_sync(0xffffffffu, dd, 1);
        if (gm < M && !(tid & 1)) {
            als_out[(long)gm * NH + head] = ds;
            ald_out[(long)gm * NH + head] = dd;
        }
    }
    #undef LOAD_A
    #undef LOAD_B
    #undef STS
}

/* ---------------- LayerNorm + FiLM ---------------- */
__global__ void k_ln_film(const float* __restrict__ ls, const float* __restrict__ lb,
                          const float* __restrict__ gam, const float* __restrict__ bet) {
    int n = (blockIdx.x * blockDim.x + threadIdx.x) >> 5;
    int lane = threadIdx.x & 31;
    if (n >= NN) return;
    float4 v = *(const float4*)(g_h + n * D + lane * 4);
    float mu = wredsum(v.x + v.y + v.z + v.w) * (1.f / 128.f);
    float d0 = v.x - mu, d1 = v.y - mu, d2 = v.z - mu, d3 = v.w - mu;
    float var = wredsum(d0 * d0 + d1 * d1 + d2 * d2 + d3 * d3) * (1.f / 128.f);
    float rs = rsqrtf(var + 1e-5f);
    float4 lsv = *(const float4*)(ls + lane * 4);
    float4 lbv = *(const float4*)(lb + lane * 4);
    float4 gv = *(const float4*)(gam + lane * 4);
    float4 bv = *(const float4*)(bet + lane * 4);
    float4 o;
    o.x = gv.x * (d0 * rs * lsv.x + lbv.x) + bv.x;
    o.y = gv.y * (d1 * rs * lsv.y + lbv.y) + bv.y;
    o.z = gv.z * (d2 * rs * lsv.z + lbv.z) + bv.z;
    o.w = gv.w * (d3 * rs * lsv.w + lbv.w) + bv.w;
    *(float4*)(g_hm + n * D + lane * 4) = o;
}

/* ---------------- edge attention vectors: warp per output ---------------- */
__global__ void k_attvec(const float* __restrict__ gWe, const float* __restrict__ gaedge) {
    int gw = blockIdx.x * 8 + (threadIdx.x >> 5);   /* 0 .. NL*128-1 */
    int lane = threadIdx.x & 31;
    int l = gw >> 7;
    int o = gw & 127;
    int h = o >> 5, f = o & 31;
    const float* We = gWe + (long)l * EFD * NH * D + (long)f * (NH * D) + h * D;
    const float* ae = gaedge + (long)l * NH * D + h * D;
    float4 w4 = *(const float4*)(We + lane * 4);
    float4 a4 = *(const float4*)(ae + lane * 4);
    float s = wredsum(w4.x * a4.x + w4.y * a4.y + w4.z * a4.z + w4.w * a4.w);
    if (lane == 0) g_v[l * NH * EFD + h * EFD + f] = s;
}
__global__ void k_aleself() {
    int l = blockIdx.x;
    int h = threadIdx.x >> 5, lane = threadIdx.x & 31;
    float s = wredsum(g_eamean[lane] * g_v[l * NH * EFD + h * EFD + lane]);
    if (lane == 0) g_aleself[l * NH + h] = s;
}

/* ---------------- per-edge attention logit al_e for ALL layers -------------- */
__global__ void k_ale_all(const float* __restrict__ ea) {
    __shared__ float sv[NL * NH * EFD];   /* 768 floats */
    __shared__ float se[128 * 33];
    int t = threadIdx.x;           /* 128 */
    long base = (long)blockIdx.x * 128;
    for (int i = t; i < NL * NH * EFD; i += 128) sv[i] = g_v[i];
    #pragma unroll
    for (int i = 0; i < 32; i++) {
        long li = (long)t + (long)i * 128;
        long gi = base * EFD + li;
        if (gi < (long)NE * EFD) {
            int row = (int)(li >> 5), col = (int)(li & 31);
            se[row * 33 + col] = ea[gi];
        }
    }
    __syncthreads();
    long j = base + t;
    if (j >= NE) return;
    float ev[EFD];
    #pragma unroll
    for (int k = 0; k < EFD; k++) ev[k] = se[t * 33 + k];
    #pragma unroll
    for (int l = 0; l < NL; l++) {
        float s0 = 0.f, s1 = 0.f, s2 = 0.f, s3 = 0.f;
        const float* v = sv + l * NH * EFD;
        #pragma unroll
        for (int k = 0; k < EFD; k++) {
            float e = ev[k];
            s0 += e * v[k];
            s1 += e * v[EFD + k];
            s2 += e * v[2 * EFD + k];
            s3 += e * v[3 * EFD + k];
        }
        float* o = g_ale + ((long)l * NE + j) * NH;
        o[0] = s0; o[1] = s1; o[2] = s2; o[3] = s3;
    }
}

/* ---------------- fused attention: softmax + gather in ONE kernel ----------- */
__global__ void k_attn(const float* __restrict__ ale_l,
                       const float* __restrict__ aleself_l,
                       const float* __restrict__ bias) {
    int n = (blockIdx.x * blockDim.x + threadIdx.x) >> 5;
    int lane = threadIdx.x & 31;
    if (n >= NN) return;
    int rb = g_rowptr[n], re = g_rowptr[n + 1];
    float4 ad = *(const float4*)(g_ald + (long)n * NH);

    float4 lw[4];
    int sreg[4];
    float4 mx = make_float4(-1e30f, -1e30f, -1e30f, -1e30f);
    #pragma unroll
    for (int j = 0; j < 4; j++) {
        int i = rb + lane + j * 32;
        lw[j] = make_float4(-1e30f, -1e30f, -1e30f, -1e30f);
        sreg[j] = 0;
        if (i < re) {
            int s = g_csrsrc[i], e = g_csreid[i];
            sreg[j] = s;
            float4 as = *(const float4*)(g_als + (long)s * NH);
            float4 ae = (e < NE) ? *(const float4*)(ale_l + (long)e * NH)
                                 : *(const float4*)aleself_l;
            float4 a; float t;
            t = as.x + ad.x + ae.x; a.x = t > 0.f ? t : 0.2f * t;
            t = as.y + ad.y + ae.y; a.y = t > 0.f ? t : 0.2f * t;
            t = as.z + ad.z + ae.z; a.z = t > 0.f ? t : 0.2f * t;
            t = as.w + ad.w + ae.w; a.w = t > 0.f ? t : 0.2f * t;
            lw[j] = a;
            mx.x = fmaxf(mx.x, a.x); mx.y = fmaxf(mx.y, a.y);
            mx.z = fmaxf(mx.z, a.z); mx.w = fmaxf(mx.w, a.w);
        }
    }
    for (int i = rb + lane + 128; i < re; i += 32) {   /* rare deg>128 spill */
        int s = g_csrsrc[i], e = g_csreid[i];
        float4 as = *(const float4*)(g_als + (long)s * NH);
        float4 ae = (e < NE) ? *(const float4*)(ale_l + (long)e * NH)
                             : *(const float4*)aleself_l;
        float4 a; float t;
        t = as.x + ad.x + ae.x; a.x = t > 0.f ? t : 0.2f * t;
        t = as.y + ad.y + ae.y; a.y = t > 0.f ? t : 0.2f * t;
        t = as.z + ad.z + ae.z; a.z = t > 0.f ? t : 0.2f * t;
        t = as.w + ad.w + ae.w; a.w = t > 0.f ? t : 0.2f * t;
        *(float4*)(g_lg + (long)i * NH) = a;
        mx.x = fmaxf(mx.x, a.x); mx.y = fmaxf(mx.y, a.y);
        mx.z = fmaxf(mx.z, a.z); mx.w = fmaxf(mx.w, a.w);
    }
    wredmax4(mx);

    float4 den = make_float4(0.f, 0.f, 0.f, 0.f);
    #pragma unroll
    for (int j = 0; j < 4; j++) {
        bool valid = (rb + lane + j * 32) < re;
        float4 a = lw[j];
        a.x = valid ? __expf(a.x - mx.x) : 0.f;
        a.y = valid ? __expf(a.y - mx.y) : 0.f;
        a.z = valid ? __expf(a.z - mx.z) : 0.f;
        a.w = valid ? __expf(a.w - mx.w) : 0.f;
        lw[j] = a;
        den.x += a.x; den.y += a.y; den.z += a.z; den.w += a.w;
    }
    for (int i = rb + lane + 128; i < re; i += 32) {
        float4 a = *(const float4*)(g_lg + (long)i * NH);
        a.x = __expf(a.x - mx.x); a.y = __expf(a.y - mx.y);
        a.z = __expf(a.z - mx.z); a.w = __expf(a.w - mx.w);
        *(float4*)(g_lg + (long)i * NH) = a;
        den.x += a.x; den.y += a.y; den.z += a.z; den.w += a.w;
    }
    wredsum4(den);
    float4 scl;
    scl.x = 0.25f / (den.x + 1e-16f);
    scl.y = 0.25f / (den.y + 1e-16f);
    scl.z = 0.25f / (den.z + 1e-16f);
    scl.w = 0.25f / (den.w + 1e-16f);

    #pragma unroll
    for (int j = 0; j < 4; j++) {
        int i = rb + lane + j * 32;
        if (i < re) {
            float4 o;
            o.x = lw[j].x * scl.x; o.y = lw[j].y * scl.y;
            o.z = lw[j].z * scl.z; o.w = lw[j].w * scl.w;
            *(float4*)(g_lg + (long)i * NH) = o;
        }
    }
    for (int i = rb + lane + 128; i < re; i += 32) {
        float4 a = *(const float4*)(g_lg + (long)i * NH);
        a.x *= scl.x; a.y *= scl.y; a.z *= scl.z; a.w *= scl.w;
        *(float4*)(g_lg + (long)i * NH) = a;
    }

    __syncwarp();   /* order g_lg writes before same-warp reads below */

    /* ---- pass B: weighted gather ---- */
    const int hh = lane >> 3;
    const int dp = (lane & 7) << 4;
    float acc[16];
    #pragma unroll
    for (int k = 0; k < 16; k++) acc[k] = 0.f;

    for (int i = rb; i < re; i++) {
        int rel = i - rb;
        int s;
        if (rel < 128) {
            int slot = rel >> 5;
            s = __shfl_sync(0xffffffffu, slot == 0 ? sreg[0] :
                            slot == 1 ? sreg[1] : slot == 2 ? sreg[2] : sreg[3],
                            rel & 31);
        } else {
            s = g_csrsrc[i];
        }
        float w = g_lg[(long)i * NH + hh];
        const __half* xp = g_x + (((long)s * NH + hh) << 7) + dp;
        uint4 r0 = *(const uint4*)xp;
        uint4 r1 = *(const uint4*)(xp + 8);
        const __half2* hp0 = (const __half2*)&r0;
        const __half2* hp1 = (const __half2*)&r1;
        #pragma unroll
        for (int q = 0; q < 4; q++) {
            float2 f = __half22float2(hp0[q]);
            acc[q * 2 + 0] += w * f.x;
            acc[q * 2 + 1] += w * f.y;
        }
        #pragma unroll
        for (int q = 0; q < 4; q++) {
            float2 f = __half22float2(hp1[q]);
            acc[8 + q * 2 + 0] += w * f.x;
            acc[8 + q * 2 + 1] += w * f.y;
        }
    }
    #pragma unroll
    for (int k = 0; k < 16; k++) {
        float vv = acc[k];
        vv += __shfl_xor_sync(0xffffffffu, vv, 8);
        vv += __shfl_xor_sync(0xffffffffu, vv, 16);
        acc[k] = vv;
    }
    if (lane < 8) {
        #pragma unroll
        for (int k = 0; k < 4; k++) {
            float4 o;
            o.x = fmaxf(acc[k * 4 + 0] + bias[dp + k * 4 + 0], 0.f);
            o.y = fmaxf(acc[k * 4 + 1] + bias[dp + k * 4 + 1], 0.f);
            o.z = fmaxf(acc[k * 4 + 2] + bias[dp + k * 4 + 2], 0.f);
            o.w = fmaxf(acc[k * 4 + 3] + bias[dp + k * 4 + 3], 0.f);
            *(float4*)(g_h + n * D + dp + k * 4) = o;
        }
    }
}

/* ---------------- fused edge head ---------------- */
__global__ void __launch_bounds__(256)
k_edge_head(const int* __restrict__ src, const int* __restrict__ dst,
            const float* __restrict__ W1, const float* __restrict__ b1,
            const float* __restrict__ W2, const float* __restrict__ b2,
            const float* __restrict__ ea, float* __restrict__ out) {
    __shared__ float sW[EFD][128];
    __shared__ float sb[128], sw2[128];
    int tid = threadIdx.x;
    for (int i = tid; i < EFD * 128; i += 256) sW[i >> 7][i & 127] = W1[256 * 128 + i];
    if (tid < 128) { sb[tid] = b1[tid]; sw2[tid] = W2[tid]; }
    __syncthreads();
    float bias2 = b2[0];
    int lane = tid & 31;
    int warp = blockIdx.x * 8 + (tid >> 5);
    int nwarps = gridDim.x * 8;
    const int NG = NE / 4;
    for (int g = warp; g < NG; g += nwarps) {
        int e = g * 4;
        float ev[4];
        float4 tu[4];
        #pragma unroll
        for (int k = 0; k < 4; k++) {
            int s = src[e + k], d = dst[e + k];
            ev[k] = ea[(long)(e + k) * EFD + lane];
            float4 tv = *(const float4*)(g_t + (long)s * D + lane * 4);
            float4 uv = *(const float4*)(g_u + (long)d * D + lane * 4);
            tu[k].x = tv.x + uv.x; tu[k].y = tv.y + uv.y;
            tu[k].z = tv.z + uv.z; tu[k].w = tv.w + uv.w;
        }
        float4 p[4];
        #pragma unroll
        for (int k = 0; k < 4; k++) p[k] = make_float4(0.f, 0.f, 0.f, 0.f);
        #pragma unroll
        for (int j = 0; j < EFD; j++) {
            float4 w = *(const float4*)&sW[j][lane * 4];
            #pragma unroll
            for (int k = 0; k < 4; k++) {
                float bj = __shfl_sync(0xffffffffu, ev[k], j);
                p[k].x += bj * w.x; p[k].y += bj * w.y;
                p[k].z += bj * w.z; p[k].w += bj * w.w;
            }
        }
        float4 bb = *(const float4*)&sb[lane * 4];
        float4 w2 = *(const float4*)&sw2[lane * 4];
        #pragma unroll
        for (int k = 0; k < 4; k++) {
            float z0 = fmaxf(tu[k].x + p[k].x + bb.x, 0.f);
            float z1 = fmaxf(tu[k].y + p[k].y + bb.y, 0.f);
            float z2 = fmaxf(tu[k].z + p[k].z + bb.z, 0.f);
            float z3 = fmaxf(tu[k].w + p[k].w + bb.w, 0.f);
            float s4 = wredsum(z0 * w2.x + z1 * w2.y + z2 * w2.z + z3 * w2.w);
            if (lane == 0) out[e + k] = s4 + bias2;
        }
    }
}

/* ---------------- host orchestration ---------------- */
extern "C" void kernel_launch(void* const* d_in, const int* in_sizes, int n_in,
                              void* d_out, int out_size) {
    const float* x      = (const float*)d_in[0];
    const int*   ei     = (const int*)  d_in[1];
    const float* ea     = (const float*)d_in[2];
    const float* gamma  = (const float*)d_in[3];
    const float* beta   = (const float*)d_in[4];
    const float* embW   = (const float*)d_in[5];
    const float* embb   = (const float*)d_in[6];
    const float* lns    = (const float*)d_in[7];
    const float* lnb    = (const float*)d_in[8];
    const float* gatW   = (const float*)d_in[9];
    const float* asrc   = (const float*)d_in[10];
    const float* adst   = (const float*)d_in[11];
    const float* gWe    = (const float*)d_in[12];
    const float* aedge  = (const float*)d_in[13];
    const float* gbias  = (const float*)d_in[14];
    const float* W1     = (const float*)d_in[15];
    const float* b1     = (const float*)d_in[16];
    const float* W2     = (const float*)d_in[17];
    const float* b2     = (const float*)d_in[18];
    float* out = (float*)d_out;

    const int* src = ei;
    const int* dst = ei + NE;

    float *p_h, *p_hm, *p_t, *p_u, *p_ale, *p_aleself, *p_als, *p_ald;
    __half* p_x;
    cudaGetSymbolAddress((void**)&p_h,  g_h);
    cudaGetSymbolAddress((void**)&p_hm, g_hm);
    cudaGetSymbolAddress((void**)&p_x,  g_x);
    cudaGetSymbolAddress((void**)&p_t,  g_t);
    cudaGetSymbolAddress((void**)&p_u,  g_u);
    cudaGetSymbolAddress((void**)&p_ale, g_ale);
    cudaGetSymbolAddress((void**)&p_aleself, g_aleself);
    cudaGetSymbolAddress((void**)&p_als, g_als);
    cudaGetSymbolAddress((void**)&p_ald, g_ald);

    const int MB = (NN + 127) / 128;   /* 196 */

    /* launches 1-3, then embed GEMM as our 4th launch (ncu lands there) */
    k_init_counts<<<(NN + 255) / 256, 256>>>();
    k_count<<<(NE + 255) / 256, 256>>>(dst);
    int nb = (NN + 1023) / 1024;
    k_scan_local<<<nb, 1024>>>();

    /* launch #4: embed GEMM — target of ncu -s 5 -c 1 (observed offset) */
    k_gemm_mma<float><<<dim3(1, MB), 256>>>(x, embW, p_h, NN, 128, embb,
                                            (const float*)0, (const float*)0,
                                            (float*)0, (float*)0, (float*)0);

    k_scan_fixup<<<1, 32>>>(nb);
    k_scan_add<<<(NN + 255) / 256, 256>>>();
    k_scatter_edges<<<(NE + 255) / 256, 256>>>(src, dst);
    k_scatter_self<<<(NN + 255) / 256, 256>>>();

    /* constants */
    k_eamean1<<<256, 128>>>(ea);
    k_eamean2<<<1, 32>>>();
    k_attvec<<<NL * 16, 256>>>(gWe, aedge);
    k_aleself<<<NL, 128>>>();
    k_ale_all<<<(NE + 127) / 128, 128>>>(ea);

    /* layers */
    for (int l = 0; l < NL; l++) {
        k_ln_film<<<(NN * 32 + 255) / 256, 256>>>(lns + l * D, lnb + l * D,
                                                  gamma + l * D, beta + l * D);
        k_gemm_mma<__half><<<dim3(4, MB), 256>>>(p_hm, gatW + (long)l * D * NH * D,
                                                 p_x, NN, 512, (const float*)0,
                                                 asrc + l * NH * D, adst + l * NH * D,
                                                 p_als, p_ald, (__half*)0);
        k_attn<<<(NN * 32 + 255) / 256, 256>>>(p_ale + (long)l * NE * NH,
                                               p_aleself + l * NH,
                                               gbias + l * D);
    }

    /* head: dual-output GEMM (t and u in one launch, 392 blocks) */
    k_gemm_mma<float><<<dim3(2, MB), 256>>>(p_h, W1, p_t, NN, 128, (const float*)0,
                                            (const float*)0, (const float*)0,
                                            (float*)0, (float*)0, p_u);
    k_edge_head<<<2048, 256>>>(src, dst, W1, b1, W2, b2, ea, out);
}

// round 12
// speedup vs baseline: 1.0245x; 1.0245x over previous
#include <cuda_runtime.h>
#include <cuda_fp16.h>
#include <mma.h>

using namespace nvcuda;

#define NN  25000
#define NE  400000
#define NEF 425000   /* NE + NN self-loops */
#define D   128
#define NH  4
#define EFD 32
#define NL  6

/* ---------------- scratch (static device globals; no allocs) -------------- */
__device__ __align__(16) float  g_h[NN * D];
__device__ __align__(16) float  g_hm[NN * D];
__device__ __align__(16) __half g_x[NN * NH * D];
__device__ __align__(16) float  g_als[NN * NH];
__device__ __align__(16) float  g_ald[NN * NH];
__device__ __align__(16) float  g_ale[NL * NE * NH];    /* all layers, edge order */
__device__ __align__(16) float  g_lg[NEF * NH];         /* CSR-order normalized weights */
__device__ int   g_rowptr[NN + 1];
__device__ int   g_counts[NN];
__device__ int   g_fill[NN];
__device__ int   g_csrsrc[NEF];
__device__ int   g_csreid[NEF];
__device__ __align__(16) float g_eamean[EFD];
__device__ __align__(16) float g_partial[256 * EFD];
__device__ __align__(16) float g_v[NL * NH * EFD];
__device__ __align__(16) float g_aleself[NL * NH];
__device__ __align__(16) float g_t[NN * D];
__device__ __align__(16) float g_u[NN * D];
__device__ int   g_bsums[32];

/* ---------------- helpers ---------------- */
__device__ __forceinline__ float wredsum(float v) {
    #pragma unroll
    for (int o = 16; o; o >>= 1) v += __shfl_xor_sync(0xffffffffu, v, o);
    return v;
}
__device__ __forceinline__ void wredsum4(float4& v) {
    #pragma unroll
    for (int o = 16; o; o >>= 1) {
        v.x += __shfl_xor_sync(0xffffffffu, v.x, o);
        v.y += __shfl_xor_sync(0xffffffffu, v.y, o);
        v.z += __shfl_xor_sync(0xffffffffu, v.z, o);
        v.w += __shfl_xor_sync(0xffffffffu, v.w, o);
    }
}
__device__ __forceinline__ void wredmax4(float4& v) {
    #pragma unroll
    for (int o = 16; o; o >>= 1) {
        v.x = fmaxf(v.x, __shfl_xor_sync(0xffffffffu, v.x, o));
        v.y = fmaxf(v.y, __shfl_xor_sync(0xffffffffu, v.y, o));
        v.z = fmaxf(v.z, __shfl_xor_sync(0xffffffffu, v.z, o));
        v.w = fmaxf(v.w, __shfl_xor_sync(0xffffffffu, v.w, o));
    }
}

/* ---------------- edge-attr mean (deterministic 2-stage) ---------------- */
__global__ void k_eamean1(const float* __restrict__ ea) {
    const int SPAN = 1563;
    int blk = blockIdx.x;
    int w = threadIdx.x >> 5, lane = threadIdx.x & 31;
    long start = (long)blk * SPAN;
    long end = start + SPAN; if (end > NE) end = NE;
    float s = 0.f;
    for (long e = start + w; e < end; e += 4) s += ea[e * EFD + lane];
    __shared__ float sm[4][32];
    sm[w][lane] = s;
    __syncthreads();
    if (w == 0) {
        float t = sm[0][lane] + sm[1][lane] + sm[2][lane] + sm[3][lane];
        g_partial[blk * 32 + lane] = t;
    }
}
__global__ void k_eamean2() {
    int lane = threadIdx.x;
    float s = 0.f;
    for (int b = 0; b < 256; b++) s += g_partial[b * 32 + lane];
    g_eamean[lane] = s * (1.f / (float)NE);
}

/* ---------------- CSR build ---------------- */
__global__ void k_init_counts() {
    int i = blockIdx.x * blockDim.x + threadIdx.x;
    if (i < NN) g_counts[i] = 1;   /* self loop */
}
__global__ void k_count(const int* __restrict__ dst) {
    int e = blockIdx.x * blockDim.x + threadIdx.x;
    if (e < NE) atomicAdd(&g_counts[dst[e]], 1);
}
__global__ void k_scan_local() {
    __shared__ int sm[1024];
    int base = blockIdx.x * 1024;
    int t = threadIdx.x;
    int v = (base + t < NN) ? g_counts[base + t] : 0;
    sm[t] = v;
    __syncthreads();
    #pragma unroll
    for (int off = 1; off < 1024; off <<= 1) {
        int x = (t >= off) ? sm[t - off] : 0;
        __syncthreads();
        sm[t] += x;
        __syncthreads();
    }
    if (base + t < NN) g_rowptr[base + t] = sm[t] - v;   /* exclusive */
    if (t == 1023) g_bsums[blockIdx.x] = sm[1023];
}
__global__ void k_scan_fixup(int nb) {
    int lane = threadIdx.x;                 /* 32 threads; nb <= 32 */
    int v = (lane < nb) ? g_bsums[lane] : 0;
    int orig = v;
    #pragma unroll
    for (int off = 1; off < 32; off <<= 1) {
        int x = __shfl_up_sync(0xffffffffu, v, off);
        if (lane >= off) v += x;
    }
    if (lane < nb) g_bsums[lane] = v - orig;   /* exclusive */
    if (lane == 31) g_rowptr[NN] = v;          /* total */
}
__global__ void k_scan_add() {
    int i = blockIdx.x * blockDim.x + threadIdx.x;
    if (i < NN) {
        int r = g_rowptr[i] + g_bsums[i >> 10];
        g_rowptr[i] = r;
        g_fill[i] = r;
    }
}
__global__ void k_scatter_edges(const int* __restrict__ src, const int* __restrict__ dst) {
    int e = blockIdx.x * blockDim.x + threadIdx.x;
    if (e < NE) {
        int d = dst[e];
        int pos = atomicAdd(&g_fill[d], 1);
        g_csrsrc[pos] = src[e];
        g_csreid[pos] = e;
    }
}
__global__ void k_scatter_self() {
    int i = blockIdx.x * blockDim.x + threadIdx.x;
    if (i < NN) {
        int pos = atomicAdd(&g_fill[i], 1);
        g_csrsrc[pos] = i;
        g_csreid[pos] = NE + i;
    }
}

/* ================= tensor-core GEMM: C[M,N] = A[M,128] @ B[128,N] =========
   fp16 HMMA, fp32 accumulate. __launch_bounds__(256,2) caps regs at 128 so
   TWO blocks co-reside per SM (R11 ncu: 142 regs -> 1 block/SM, occ 12%,
   issue 9% — pure latency bound). Optional fused attention dots (av/dv);
   optional dual-output mode (C2). All shuffles warp-uniform. */

#define AS_H 5120      /* halves per A stage: 128*40 */
#define BS_H 4352      /* halves per B stage: 32*136 */
#define SMEM_BYTES 37888

__device__ __forceinline__ void cvt_sts(__half* dst, const float4* p) {
    __half2 h[8];
    h[0] = __floats2half2_rn(p[0].x, p[0].y);
    h[1] = __floats2half2_rn(p[0].z, p[0].w);
    h[2] = __floats2half2_rn(p[1].x, p[1].y);
    h[3] = __floats2half2_rn(p[1].z, p[1].w);
    h[4] = __floats2half2_rn(p[2].x, p[2].y);
    h[5] = __floats2half2_rn(p[2].z, p[2].w);
    h[6] = __floats2half2_rn(p[3].x, p[3].y);
    h[7] = __floats2half2_rn(p[3].z, p[3].w);
    *(uint4*)dst       = *(const uint4*)&h[0];
    *(uint4*)(dst + 8) = *(const uint4*)&h[4];
}

template <typename OutT>
__global__ void __launch_bounds__(256, 2)
k_gemm_mma(const float* __restrict__ A, const float* __restrict__ B,
           OutT* __restrict__ C, int M, int N, const float* __restrict__ bias,
           const float* __restrict__ av, const float* __restrict__ dv,
           float* __restrict__ als_out, float* __restrict__ ald_out,
           OutT* __restrict__ C2) {
    __shared__ __align__(16) char smem[SMEM_BYTES];
    __half* As = (__half*)smem;                 /* [2][128][40] */
    __half* Bs = (__half*)(smem + 20480);       /* [2][32][136] */
    float*  Cs = (float*)smem;                  /* [128][72] epilogue reuse */

    const int tid = threadIdx.x;
    const int bm = blockIdx.y * 128;
    const int bn = C2 ? 0 : blockIdx.x * 128;
    if (C2 && blockIdx.x == 1) { B += 128 * 128; C = C2; }
    const int warp = tid >> 5;
    const int wm = warp >> 1;      /* 0..3 */
    const int wn = warp & 1;       /* 0..1 */

    const int r_a = tid >> 1, ca = (tid & 1) * 16;
    const int r_b = tid >> 3, cb = (tid & 7) * 16;
    const bool arow_ok = (bm + r_a) < M;
    const float* Aptr = A + (long)(bm + r_a) * 128 + ca;
    const float* Bptr = B + (long)r_b * N + bn + cb;

    float4 pa[4], pb[4];
    #define LOAD_A(kk) do { \
        if (arow_ok) { \
            pa[0] = *(const float4*)(Aptr + (kk)); \
            pa[1] = *(const float4*)(Aptr + (kk) + 4); \
            pa[2] = *(const float4*)(Aptr + (kk) + 8); \
            pa[3] = *(const float4*)(Aptr + (kk) + 12); \
        } else { pa[0] = pa[1] = pa[2] = pa[3] = make_float4(0.f,0.f,0.f,0.f); } \
    } while (0)
    #define LOAD_B(kk) do { \
        const float* bp = Bptr + (long)(kk) * N; \
        pb[0] = *(const float4*)bp; \
        pb[1] = *(const float4*)(bp + 4); \
        pb[2] = *(const float4*)(bp + 8); \
        pb[3] = *(const float4*)(bp + 12); \
    } while (0)
    #define STS(st) do { \
        cvt_sts(As + (st) * AS_H + r_a * 40 + ca, pa); \
        cvt_sts(Bs + (st) * BS_H + r_b * 136 + cb, pb); \
    } while (0)

    wmma::fragment<wmma::accumulator, 16, 16, 16, float> cf[2][4];
    #pragma unroll
    for (int i = 0; i < 2; i++)
        #pragma unroll
        for (int j = 0; j < 4; j++) wmma::fill_fragment(cf[i][j], 0.f);

    LOAD_A(0); LOAD_B(0);
    STS(0);
    __syncthreads();

    #pragma unroll
    for (int t = 0; t < 4; t++) {
        if (t < 3) { LOAD_A((t + 1) * 32); LOAD_B((t + 1) * 32); }
        const int st = t & 1;
        #pragma unroll
        for (int ks = 0; ks < 2; ks++) {
            wmma::fragment<wmma::matrix_a, 16, 16, 16, __half, wmma::row_major> af0, af1;
            wmma::load_matrix_sync(af0, As + st * AS_H + (wm * 32) * 40 + ks * 16, 40);
            wmma::load_matrix_sync(af1, As + st * AS_H + (wm * 32 + 16) * 40 + ks * 16, 40);
            #pragma unroll
            for (int j = 0; j < 4; j++) {
                wmma::fragment<wmma::matrix_b, 16, 16, 16, __half, wmma::row_major> bf;
                wmma::load_matrix_sync(bf, Bs + st * BS_H + (ks * 16) * 136 + wn * 64 + j * 16, 136);
                wmma::mma_sync(cf[0][j], af0, bf, cf[0][j]);
                wmma::mma_sync(cf[1][j], af1, bf, cf[1][j]);
            }
        }
        if (t < 3) {
            __syncthreads();
            STS((t + 1) & 1);
            __syncthreads();
        }
    }

    /* epilogue: two phases through smem (Cs reuses As/Bs) */
    const int r = tid >> 1;
    const int gm = bm + r;
    const int head = blockIdx.x;                     /* valid for N=512 x-GEMM */
    float ds = 0.f, dd = 0.f;

    #pragma unroll
    for (int ph = 0; ph < 2; ph++) {
        __syncthreads();
        #pragma unroll
        for (int i = 0; i < 2; i++)
            #pragma unroll
            for (int q = 0; q < 2; q++)
                wmma::store_matrix_sync(Cs + (wm * 32 + i * 16) * 72 + wn * 32 + q * 16,
                                        cf[i][ph * 2 + q], 72, wmma::mem_row_major);
        __syncthreads();
        int c0 = (tid & 1) * 32;
        if (gm < M) {
            const float* srow = Cs + r * 72 + c0;
            int colb = (c0 ? 64 : 0) + ph * 32;      /* column within 128 */
            int gnb = bn + colb;
            #pragma unroll
            for (int c = 0; c < 32; c += 4) {
                float4 v = *(const float4*)(srow + c);
                if (bias) {
                    v.x += bias[gnb + c + 0];
                    v.y += bias[gnb + c + 1];
                    v.z += bias[gnb + c + 2];
                    v.w += bias[gnb + c + 3];
                }
                if (av) {
                    float4 a4 = *(const float4*)(av + head * D + colb + c);
                    float4 b4 = *(const float4*)(dv + head * D + colb + c);
                    ds += v.x * a4.x + v.y * a4.y + v.z * a4.z + v.w * a4.w;
                    dd += v.x * b4.x + v.y * b4.y + v.z * b4.z + v.w * b4.w;
                }
                if (sizeof(OutT) == 4) {
                    *(float4*)((float*)C + (long)gm * N + gnb + c) = v;
                } else {
                    __half2 h0 = __floats2half2_rn(v.x, v.y);
                    __half2 h1 = __floats2half2_rn(v.z, v.w);
                    uint2 u; u.x = *(unsigned*)&h0; u.y = *(unsigned*)&h1;
                    *(uint2*)((__half*)C + (long)gm * N + gnb + c) = u;
                }
            }
        }
    }
    /* warp-uniform shuffle: executed by ALL lanes (av is uniform) */
    if (av) {
        ds += __shfl_xor_sync(0xffffffffu, ds, 1);
        dd += __shfl_xor_sync(0xffffffffu, dd, 1);
        if (gm < M && !(tid & 1)) {
            als_out[(long)gm * NH + head] = ds;
            ald_out[(long)gm * NH + head] = dd;
        }
    }
    #undef LOAD_A
    #undef LOAD_B
    #undef STS
}

/* ---------------- LayerNorm + FiLM ---------------- */
__global__ void k_ln_film(const float* __restrict__ ls, const float* __restrict__ lb,
                          const float* __restrict__ gam, const float* __restrict__ bet) {
    int n = (blockIdx.x * blockDim.x + threadIdx.x) >> 5;
    int lane = threadIdx.x & 31;
    if (n >= NN) return;
    float4 v = *(const float4*)(g_h + n * D + lane * 4);
    float mu = wredsum(v.x + v.y + v.z + v.w) * (1.f / 128.f);
    float d0 = v.x - mu, d1 = v.y - mu, d2 = v.z - mu, d3 = v.w - mu;
    float var = wredsum(d0 * d0 + d1 * d1 + d2 * d2 + d3 * d3) * (1.f / 128.f);
    float rs = rsqrtf(var + 1e-5f);
    float4 lsv = *(const float4*)(ls + lane * 4);
    float4 lbv = *(const float4*)(lb + lane * 4);
    float4 gv = *(const float4*)(gam + lane * 4);
    float4 bv = *(const float4*)(bet + lane * 4);
    float4 o;
    o.x = gv.x * (d0 * rs * lsv.x + lbv.x) + bv.x;
    o.y = gv.y * (d1 * rs * lsv.y + lbv.y) + bv.y;
    o.z = gv.z * (d2 * rs * lsv.z + lbv.z) + bv.z;
    o.w = gv.w * (d3 * rs * lsv.w + lbv.w) + bv.w;
    *(float4*)(g_hm + n * D + lane * 4) = o;
}

/* ---------------- edge attention vectors: warp per output ---------------- */
__global__ void k_attvec(const float* __restrict__ gWe, const float* __restrict__ gaedge) {
    int gw = blockIdx.x * 8 + (threadIdx.x >> 5);   /* 0 .. NL*128-1 */
    int lane = threadIdx.x & 31;
    int l = gw >> 7;
    int o = gw & 127;
    int h = o >> 5, f = o & 31;
    const float* We = gWe + (long)l * EFD * NH * D + (long)f * (NH * D) + h * D;
    const float* ae = gaedge + (long)l * NH * D + h * D;
    float4 w4 = *(const float4*)(We + lane * 4);
    float4 a4 = *(const float4*)(ae + lane * 4);
    float s = wredsum(w4.x * a4.x + w4.y * a4.y + w4.z * a4.z + w4.w * a4.w);
    if (lane == 0) g_v[l * NH * EFD + h * EFD + f] = s;
}
__global__ void k_aleself() {
    int l = blockIdx.x;
    int h = threadIdx.x >> 5, lane = threadIdx.x & 31;
    float s = wredsum(g_eamean[lane] * g_v[l * NH * EFD + h * EFD + lane]);
    if (lane == 0) g_aleself[l * NH + h] = s;
}

/* ---------------- per-edge attention logit al_e for ALL layers -------------- */
__global__ void k_ale_all(const float* __restrict__ ea) {
    __shared__ float sv[NL * NH * EFD];   /* 768 floats */
    __shared__ float se[128 * 33];
    int t = threadIdx.x;           /* 128 */
    long base = (long)blockIdx.x * 128;
    for (int i = t; i < NL * NH * EFD; i += 128) sv[i] = g_v[i];
    #pragma unroll
    for (int i = 0; i < 32; i++) {
        long li = (long)t + (long)i * 128;
        long gi = base * EFD + li;
        if (gi < (long)NE * EFD) {
            int row = (int)(li >> 5), col = (int)(li & 31);
            se[row * 33 + col] = ea[gi];
        }
    }
    __syncthreads();
    long j = base + t;
    if (j >= NE) return;
    float ev[EFD];
    #pragma unroll
    for (int k = 0; k < EFD; k++) ev[k] = se[t * 33 + k];
    #pragma unroll
    for (int l = 0; l < NL; l++) {
        float s0 = 0.f, s1 = 0.f, s2 = 0.f, s3 = 0.f;
        const float* v = sv + l * NH * EFD;
        #pragma unroll
        for (int k = 0; k < EFD; k++) {
            float e = ev[k];
            s0 += e * v[k];
            s1 += e * v[EFD + k];
            s2 += e * v[2 * EFD + k];
            s3 += e * v[3 * EFD + k];
        }
        float* o = g_ale + ((long)l * NE + j) * NH;
        o[0] = s0; o[1] = s1; o[2] = s2; o[3] = s3;
    }
}

/* ---------------- fused attention: softmax + gather in ONE kernel ----------- */
__global__ void k_attn(const float* __restrict__ ale_l,
                       const float* __restrict__ aleself_l,
                       const float* __restrict__ bias) {
    int n = (blockIdx.x * blockDim.x + threadIdx.x) >> 5;
    int lane = threadIdx.x & 31;
    if (n >= NN) return;
    int rb = g_rowptr[n], re = g_rowptr[n + 1];
    float4 ad = *(const float4*)(g_ald + (long)n * NH);

    float4 lw[4];
    int sreg[4];
    float4 mx = make_float4(-1e30f, -1e30f, -1e30f, -1e30f);
    #pragma unroll
    for (int j = 0; j < 4; j++) {
        int i = rb + lane + j * 32;
        lw[j] = make_float4(-1e30f, -1e30f, -1e30f, -1e30f);
        sreg[j] = 0;
        if (i < re) {
            int s = g_csrsrc[i], e = g_csreid[i];
            sreg[j] = s;
            float4 as = *(const float4*)(g_als + (long)s * NH);
            float4 ae = (e < NE) ? *(const float4*)(ale_l + (long)e * NH)
                                 : *(const float4*)aleself_l;
            float4 a; float t;
            t = as.x + ad.x + ae.x; a.x = t > 0.f ? t : 0.2f * t;
            t = as.y + ad.y + ae.y; a.y = t > 0.f ? t : 0.2f * t;
            t = as.z + ad.z + ae.z; a.z = t > 0.f ? t : 0.2f * t;
            t = as.w + ad.w + ae.w; a.w = t > 0.f ? t : 0.2f * t;
            lw[j] = a;
            mx.x = fmaxf(mx.x, a.x); mx.y = fmaxf(mx.y, a.y);
            mx.z = fmaxf(mx.z, a.z); mx.w = fmaxf(mx.w, a.w);
        }
    }
    for (int i = rb + lane + 128; i < re; i += 32) {   /* rare deg>128 spill */
        int s = g_csrsrc[i], e = g_csreid[i];
        float4 as = *(const float4*)(g_als + (long)s * NH);
        float4 ae = (e < NE) ? *(const float4*)(ale_l + (long)e * NH)
                             : *(const float4*)aleself_l;
        float4 a; float t;
        t = as.x + ad.x + ae.x; a.x = t > 0.f ? t : 0.2f * t;
        t = as.y + ad.y + ae.y; a.y = t > 0.f ? t : 0.2f * t;
        t = as.z + ad.z + ae.z; a.z = t > 0.f ? t : 0.2f * t;
        t = as.w + ad.w + ae.w; a.w = t > 0.f ? t : 0.2f * t;
        *(float4*)(g_lg + (long)i * NH) = a;
        mx.x = fmaxf(mx.x, a.x); mx.y = fmaxf(mx.y, a.y);
        mx.z = fmaxf(mx.z, a.z); mx.w = fmaxf(mx.w, a.w);
    }
    wredmax4(mx);

    float4 den = make_float4(0.f, 0.f, 0.f, 0.f);
    #pragma unroll
    for (int j = 0; j < 4; j++) {
        bool valid = (rb + lane + j * 32) < re;
        float4 a = lw[j];
        a.x = valid ? __expf(a.x - mx.x) : 0.f;
        a.y = valid ? __expf(a.y - mx.y) : 0.f;
        a.z = valid ? __expf(a.z - mx.z) : 0.f;
        a.w = valid ? __expf(a.w - mx.w) : 0.f;
        lw[j] = a;
        den.x += a.x; den.y += a.y; den.z += a.z; den.w += a.w;
    }
    for (int i = rb + lane + 128; i < re; i += 32) {
        float4 a = *(const float4*)(g_lg + (long)i * NH);
        a.x = __expf(a.x - mx.x); a.y = __expf(a.y - mx.y);
        a.z = __expf(a.z - mx.z); a.w = __expf(a.w - mx.w);
        *(float4*)(g_lg + (long)i * NH) = a;
        den.x += a.x; den.y += a.y; den.z += a.z; den.w += a.w;
    }
    wredsum4(den);
    float4 scl;
    scl.x = 0.25f / (den.x + 1e-16f);
    scl.y = 0.25f / (den.y + 1e-16f);
    scl.z = 0.25f / (den.z + 1e-16f);
    scl.w = 0.25f / (den.w + 1e-16f);

    #pragma unroll
    for (int j = 0; j < 4; j++) {
        int i = rb + lane + j * 32;
        if (i < re) {
            float4 o;
            o.x = lw[j].x * scl.x; o.y = lw[j].y * scl.y;
            o.z = lw[j].z * scl.z; o.w = lw[j].w * scl.w;
            *(float4*)(g_lg + (long)i * NH) = o;
        }
    }
    for (int i = rb + lane + 128; i < re; i += 32) {
        float4 a = *(const float4*)(g_lg + (long)i * NH);
        a.x *= scl.x; a.y *= scl.y; a.z *= scl.z; a.w *= scl.w;
        *(float4*)(g_lg + (long)i * NH) = a;
    }

    __syncwarp();   /* order g_lg writes before same-warp reads below */

    /* ---- pass B: weighted gather ---- */
    const int hh = lane >> 3;
    const int dp = (lane & 7) << 4;
    float acc[16];
    #pragma unroll
    for (int k = 0; k < 16; k++) acc[k] = 0.f;

    for (int i = rb; i < re; i++) {
        int rel = i - rb;
        int s;
        if (rel < 128) {
            int slot = rel >> 5;
            s = __shfl_sync(0xffffffffu, slot == 0 ? sreg[0] :
                            slot == 1 ? sreg[1] : slot == 2 ? sreg[2] : sreg[3],
                            rel & 31);
        } else {
            s = g_csrsrc[i];
        }
        float w = g_lg[(long)i * NH + hh];
        const __half* xp = g_x + (((long)s * NH + hh) << 7) + dp;
        uint4 r0 = *(const uint4*)xp;
        uint4 r1 = *(const uint4*)(xp + 8);
        const __half2* hp0 = (const __half2*)&r0;
        const __half2* hp1 = (const __half2*)&r1;
        #pragma unroll
        for (int q = 0; q < 4; q++) {
            float2 f = __half22float2(hp0[q]);
            acc[q * 2 + 0] += w * f.x;
            acc[q * 2 + 1] += w * f.y;
        }
        #pragma unroll
        for (int q = 0; q < 4; q++) {
            float2 f = __half22float2(hp1[q]);
            acc[8 + q * 2 + 0] += w * f.x;
            acc[8 + q * 2 + 1] += w * f.y;
        }
    }
    #pragma unroll
    for (int k = 0; k < 16; k++) {
        float vv = acc[k];
        vv += __shfl_xor_sync(0xffffffffu, vv, 8);
        vv += __shfl_xor_sync(0xffffffffu, vv, 16);
        acc[k] = vv;
    }
    if (lane < 8) {
        #pragma unroll
        for (int k = 0; k < 4; k++) {
            float4 o;
            o.x = fmaxf(acc[k * 4 + 0] + bias[dp + k * 4 + 0], 0.f);
            o.y = fmaxf(acc[k * 4 + 1] + bias[dp + k * 4 + 1], 0.f);
            o.z = fmaxf(acc[k * 4 + 2] + bias[dp + k * 4 + 2], 0.f);
            o.w = fmaxf(acc[k * 4 + 3] + bias[dp + k * 4 + 3], 0.f);
            *(float4*)(g_h + n * D + dp + k * 4) = o;
        }
    }
}

/* ---------------- fused edge head ---------------- */
__global__ void __launch_bounds__(256)
k_edge_head(const int* __restrict__ src, const int* __restrict__ dst,
            const float* __restrict__ W1, const float* __restrict__ b1,
            const float* __restrict__ W2, const float* __restrict__ b2,
            const float* __restrict__ ea, float* __restrict__ out) {
    __shared__ float sW[EFD][128];
    __shared__ float sb[128], sw2[128];
    int tid = threadIdx.x;
    for (int i = tid; i < EFD * 128; i += 256) sW[i >> 7][i & 127] = W1[256 * 128 + i];
    if (tid < 128) { sb[tid] = b1[tid]; sw2[tid] = W2[tid]; }
    __syncthreads();
    float bias2 = b2[0];
    int lane = tid & 31;
    int warp = blockIdx.x * 8 + (tid >> 5);
    int nwarps = gridDim.x * 8;
    const int NG = NE / 4;
    for (int g = warp; g < NG; g += nwarps) {
        int e = g * 4;
        float ev[4];
        float4 tu[4];
        #pragma unroll
        for (int k = 0; k < 4; k++) {
            int s = src[e + k], d = dst[e + k];
            ev[k] = ea[(long)(e + k) * EFD + lane];
            float4 tv = *(const float4*)(g_t + (long)s * D + lane * 4);
            float4 uv = *(const float4*)(g_u + (long)d * D + lane * 4);
            tu[k].x = tv.x + uv.x; tu[k].y = tv.y + uv.y;
            tu[k].z = tv.z + uv.z; tu[k].w = tv.w + uv.w;
        }
        float4 p[4];
        #pragma unroll
        for (int k = 0; k < 4; k++) p[k] = make_float4(0.f, 0.f, 0.f, 0.f);
        #pragma unroll
        for (int j = 0; j < EFD; j++) {
            float4 w = *(const float4*)&sW[j][lane * 4];
            #pragma unroll
            for (int k = 0; k < 4; k++) {
                float bj = __shfl_sync(0xffffffffu, ev[k], j);
                p[k].x += bj * w.x; p[k].y += bj * w.y;
                p[k].z += bj * w.z; p[k].w += bj * w.w;
            }
        }
        float4 bb = *(const float4*)&sb[lane * 4];
        float4 w2 = *(const float4*)&sw2[lane * 4];
        #pragma unroll
        for (int k = 0; k < 4; k++) {
            float z0 = fmaxf(tu[k].x + p[k].x + bb.x, 0.f);
            float z1 = fmaxf(tu[k].y + p[k].y + bb.y, 0.f);
            float z2 = fmaxf(tu[k].z + p[k].z + bb.z, 0.f);
            float z3 = fmaxf(tu[k].w + p[k].w + bb.w, 0.f);
            float s4 = wredsum(z0 * w2.x + z1 * w2.y + z2 * w2.z + z3 * w2.w);
            if (lane == 0) out[e + k] = s4 + bias2;
        }
    }
}

/* ---------------- host orchestration ---------------- */
extern "C" void kernel_launch(void* const* d_in, const int* in_sizes, int n_in,
                              void* d_out, int out_size) {
    const float* x      = (const float*)d_in[0];
    const int*   ei     = (const int*)  d_in[1];
    const float* ea     = (const float*)d_in[2];
    const float* gamma  = (const float*)d_in[3];
    const float* beta   = (const float*)d_in[4];
    const float* embW   = (const float*)d_in[5];
    const float* embb   = (const float*)d_in[6];
    const float* lns    = (const float*)d_in[7];
    const float* lnb    = (const float*)d_in[8];
    const float* gatW   = (const float*)d_in[9];
    const float* asrc   = (const float*)d_in[10];
    const float* adst   = (const float*)d_in[11];
    const float* gWe    = (const float*)d_in[12];
    const float* aedge  = (const float*)d_in[13];
    const float* gbias  = (const float*)d_in[14];
    const float* W1     = (const float*)d_in[15];
    const float* b1     = (const float*)d_in[16];
    const float* W2     = (const float*)d_in[17];
    const float* b2     = (const float*)d_in[18];
    float* out = (float*)d_out;

    const int* src = ei;
    const int* dst = ei + NE;

    float *p_h, *p_hm, *p_t, *p_u, *p_ale, *p_aleself, *p_als, *p_ald;
    __half* p_x;
    cudaGetSymbolAddress((void**)&p_h,  g_h);
    cudaGetSymbolAddress((void**)&p_hm, g_hm);
    cudaGetSymbolAddress((void**)&p_x,  g_x);
    cudaGetSymbolAddress((void**)&p_t,  g_t);
    cudaGetSymbolAddress((void**)&p_u,  g_u);
    cudaGetSymbolAddress((void**)&p_ale, g_ale);
    cudaGetSymbolAddress((void**)&p_aleself, g_aleself);
    cudaGetSymbolAddress((void**)&p_als, g_als);
    cudaGetSymbolAddress((void**)&p_ald, g_ald);

    const int MB = (NN + 127) / 128;   /* 196 */

    /* launches 1-3, then embed GEMM as our 4th launch (ncu lands there) */
    k_init_counts<<<(NN + 255) / 256, 256>>>();
    k_count<<<(NE + 255) / 256, 256>>>(dst);
    int nb = (NN + 1023) / 1024;
    k_scan_local<<<nb, 1024>>>();

    /* launch #4: embed GEMM — target of ncu -s 5 -c 1 (observed offset) */
    k_gemm_mma<float><<<dim3(1, MB), 256>>>(x, embW, p_h, NN, 128, embb,
                                            (const float*)0, (const float*)0,
                                            (float*)0, (float*)0, (float*)0);

    k_scan_fixup<<<1, 32>>>(nb);
    k_scan_add<<<(NN + 255) / 256, 256>>>();
    k_scatter_edges<<<(NE + 255) / 256, 256>>>(src, dst);
    k_scatter_self<<<(NN + 255) / 256, 256>>>();

    /* constants */
    k_eamean1<<<256, 128>>>(ea);
    k_eamean2<<<1, 32>>>();
    k_attvec<<<NL * 16, 256>>>(gWe, aedge);
    k_aleself<<<NL, 128>>>();
    k_ale_all<<<(NE + 127) / 128, 128>>>(ea);

    /* layers */
    for (int l = 0; l < NL; l++) {
        k_ln_film<<<(NN * 32 + 255) / 256, 256>>>(lns + l * D, lnb + l * D,
                                                  gamma + l * D, beta + l * D);
        k_gemm_mma<__half><<<dim3(4, MB), 256>>>(p_hm, gatW + (long)l * D * NH * D,
                                                 p_x, NN, 512, (const float*)0,
                                                 asrc + l * NH * D, adst + l * NH * D,
                                                 p_als, p_ald, (__half*)0);
        k_attn<<<(NN * 32 + 255) / 256, 256>>>(p_ale + (long)l * NE * NH,
                                               p_aleself + l * NH,
                                               gbias + l * D);
    }

    /* head: dual-output GEMM (t and u in one launch, 392 blocks) */
    k_gemm_mma<float><<<dim3(2, MB), 256>>>(p_h, W1, p_t, NN, 128, (const float*)0,
                                            (const float*)0, (const float*)0,
                                            (float*)0, (float*)0, p_u);
    k_edge_head<<<2048, 256>>>(src, dst, W1, b1, W2, b2, ea, out);
}

// round 13
// speedup vs baseline: 1.0893x; 1.0633x over previous
#include <cuda_runtime.h>
#include <cuda_fp16.h>
#include <mma.h>

using namespace nvcuda;

#define NN  25000
#define NE  400000
#define NEF 425000   /* NE + NN self-loops */
#define D   128
#define NH  4
#define EFD 32
#define NL  6

/* ---------------- scratch (static device globals; no allocs) -------------- */
__device__ __align__(16) float  g_h[NN * D];
__device__ __align__(16) __half g_hm[NN * D];          /* LN output, fp16 */
__device__ __align__(16) __half g_xh[NN * D];          /* fp16 x / fp16 h for head */
__device__ __align__(16) __half g_x[NN * NH * D];
__device__ __align__(16) __half g_wh[NL * D * NH * D]; /* gatW fp16 */
__device__ __align__(16) __half g_ewh[D * D];          /* embW fp16 */
__device__ __align__(16) __half g_w1h[2 * D * D];      /* W1 t/u slices fp16 */
__device__ __align__(16) float  g_als[NN * NH];
__device__ __align__(16) float  g_ald[NN * NH];
__device__ __align__(16) float  g_ale[NL * NE * NH];
__device__ __align__(16) float  g_lg[NEF * NH];
__device__ int   g_rowptr[NN + 1];
__device__ int   g_counts[NN];
__device__ int   g_fill[NN];
__device__ int   g_csrsrc[NEF];
__device__ int   g_csreid[NEF];
__device__ __align__(16) float g_eamean[EFD];
__device__ __align__(16) float g_partial[256 * EFD];
__device__ __align__(16) float g_v[NL * NH * EFD];
__device__ __align__(16) float g_aleself[NL * NH];
__device__ __align__(16) float g_t[NN * D];
__device__ __align__(16) float g_u[NN * D];
__device__ int   g_bsums[32];

/* ---------------- helpers ---------------- */
__device__ __forceinline__ float wredsum(float v) {
    #pragma unroll
    for (int o = 16; o; o >>= 1) v += __shfl_xor_sync(0xffffffffu, v, o);
    return v;
}
__device__ __forceinline__ void wredsum4(float4& v) {
    #pragma unroll
    for (int o = 16; o; o >>= 1) {
        v.x += __shfl_xor_sync(0xffffffffu, v.x, o);
        v.y += __shfl_xor_sync(0xffffffffu, v.y, o);
        v.z += __shfl_xor_sync(0xffffffffu, v.z, o);
        v.w += __shfl_xor_sync(0xffffffffu, v.w, o);
    }
}
__device__ __forceinline__ void wredmax4(float4& v) {
    #pragma unroll
    for (int o = 16; o; o >>= 1) {
        v.x = fmaxf(v.x, __shfl_xor_sync(0xffffffffu, v.x, o));
        v.y = fmaxf(v.y, __shfl_xor_sync(0xffffffffu, v.y, o));
        v.z = fmaxf(v.z, __shfl_xor_sync(0xffffffffu, v.z, o));
        v.w = fmaxf(v.w, __shfl_xor_sync(0xffffffffu, v.w, o));
    }
}

/* ---------------- fp32 -> fp16 bulk convert ---------------- */
__global__ void k_f2h(const float* __restrict__ src, __half* __restrict__ dst, int n) {
    int i = (blockIdx.x * blockDim.x + threadIdx.x) * 4;
    if (i < n) {
        float4 v = *(const float4*)(src + i);
        __half2 h0 = __floats2half2_rn(v.x, v.y);
        __half2 h1 = __floats2half2_rn(v.z, v.w);
        uint2 u; u.x = *(unsigned*)&h0; u.y = *(unsigned*)&h1;
        *(uint2*)(dst + i) = u;
    }
}

/* ---------------- edge-attr mean (deterministic 2-stage) ---------------- */
__global__ void k_eamean1(const float* __restrict__ ea) {
    const int SPAN = 1563;
    int blk = blockIdx.x;
    int w = threadIdx.x >> 5, lane = threadIdx.x & 31;
    long start = (long)blk * SPAN;
    long end = start + SPAN; if (end > NE) end = NE;
    float s = 0.f;
    for (long e = start + w; e < end; e += 4) s += ea[e * EFD + lane];
    __shared__ float sm[4][32];
    sm[w][lane] = s;
    __syncthreads();
    if (w == 0) {
        float t = sm[0][lane] + sm[1][lane] + sm[2][lane] + sm[3][lane];
        g_partial[blk * 32 + lane] = t;
    }
}
__global__ void k_eamean2() {
    int lane = threadIdx.x;
    float s = 0.f;
    for (int b = 0; b < 256; b++) s += g_partial[b * 32 + lane];
    g_eamean[lane] = s * (1.f / (float)NE);
}

/* ---------------- CSR build ---------------- */
__global__ void k_init_counts() {
    int i = blockIdx.x * blockDim.x + threadIdx.x;
    if (i < NN) g_counts[i] = 1;   /* self loop */
}
__global__ void k_count(const int* __restrict__ dst) {
    int e = blockIdx.x * blockDim.x + threadIdx.x;
    if (e < NE) atomicAdd(&g_counts[dst[e]], 1);
}
__global__ void k_scan_local() {
    __shared__ int sm[1024];
    int base = blockIdx.x * 1024;
    int t = threadIdx.x;
    int v = (base + t < NN) ? g_counts[base + t] : 0;
    sm[t] = v;
    __syncthreads();
    #pragma unroll
    for (int off = 1; off < 1024; off <<= 1) {
        int x = (t >= off) ? sm[t - off] : 0;
        __syncthreads();
        sm[t] += x;
        __syncthreads();
    }
    if (base + t < NN) g_rowptr[base + t] = sm[t] - v;   /* exclusive */
    if (t == 1023) g_bsums[blockIdx.x] = sm[1023];
}
__global__ void k_scan_fixup(int nb) {
    int lane = threadIdx.x;                 /* 32 threads; nb <= 32 */
    int v = (lane < nb) ? g_bsums[lane] : 0;
    int orig = v;
    #pragma unroll
    for (int off = 1; off < 32; off <<= 1) {
        int x = __shfl_up_sync(0xffffffffu, v, off);
        if (lane >= off) v += x;
    }
    if (lane < nb) g_bsums[lane] = v - orig;   /* exclusive */
    if (lane == 31) g_rowptr[NN] = v;          /* total */
}
__global__ void k_scan_add() {
    int i = blockIdx.x * blockDim.x + threadIdx.x;
    if (i < NN) {
        int r = g_rowptr[i] + g_bsums[i >> 10];
        g_rowptr[i] = r;
        g_fill[i] = r;
    }
}
__global__ void k_scatter_edges(const int* __restrict__ src, const int* __restrict__ dst) {
    int e = blockIdx.x * blockDim.x + threadIdx.x;
    if (e < NE) {
        int d = dst[e];
        int pos = atomicAdd(&g_fill[d], 1);
        g_csrsrc[pos] = src[e];
        g_csreid[pos] = e;
    }
}
__global__ void k_scatter_self() {
    int i = blockIdx.x * blockDim.x + threadIdx.x;
    if (i < NN) {
        int pos = atomicAdd(&g_fill[i], 1);
        g_csrsrc[pos] = i;
        g_csreid[pos] = NE + i;
    }
}

/* ================= tensor-core GEMM: C[M,N] = A[M,128] @ B[128,N] =========
   fp16 operands PRE-CONVERTED in global memory (no in-kernel cvt); fp32
   accumulate. __launch_bounds__(256,2) for 2 blocks/SM. Optional fused
   attention dots (av/dv); optional dual-output mode (C2). */

#define AS_H 5120      /* halves per A stage: 128*40 */
#define BS_H 4352      /* halves per B stage: 32*136 */
#define SMEM_BYTES 37888

template <typename OutT>
__global__ void __launch_bounds__(256, 2)
k_gemm_mma(const __half* __restrict__ A, const __half* __restrict__ B,
           OutT* __restrict__ C, int M, int N, const float* __restrict__ bias,
           const float* __restrict__ av, const float* __restrict__ dv,
           float* __restrict__ als_out, float* __restrict__ ald_out,
           OutT* __restrict__ C2) {
    __shared__ __align__(16) char smem[SMEM_BYTES];
    __half* As = (__half*)smem;                 /* [2][128][40] */
    __half* Bs = (__half*)(smem + 20480);       /* [2][32][136] */
    float*  Cs = (float*)smem;                  /* [128][72] epilogue reuse */

    const int tid = threadIdx.x;
    const int bm = blockIdx.y * 128;
    const int bn = C2 ? 0 : blockIdx.x * 128;
    if (C2 && blockIdx.x == 1) { B += 128 * 128; C = C2; }
    const int warp = tid >> 5;
    const int wm = warp >> 1;      /* 0..3 */
    const int wn = warp & 1;       /* 0..1 */

    const int r_a = tid >> 1, ca = (tid & 1) * 16;
    const int r_b = tid >> 3, cb = (tid & 7) * 16;
    const bool arow_ok = (bm + r_a) < M;
    const __half* Aptr = A + (long)(bm + r_a) * 128 + ca;
    const __half* Bptr = B + (long)r_b * N + bn + cb;

    uint4 pa0, pa1, pb0, pb1;
    #define LOAD_A(kk) do { \
        if (arow_ok) { \
            pa0 = *(const uint4*)(Aptr + (kk)); \
            pa1 = *(const uint4*)(Aptr + (kk) + 8); \
        } else { pa0 = make_uint4(0,0,0,0); pa1 = pa0; } \
    } while (0)
    #define LOAD_B(kk) do { \
        const __half* bp = Bptr + (long)(kk) * N; \
        pb0 = *(const uint4*)bp; \
        pb1 = *(const uint4*)(bp + 8); \
    } while (0)
    #define STS(st) do { \
        *(uint4*)(As + (st) * AS_H + r_a * 40 + ca) = pa0; \
        *(uint4*)(As + (st) * AS_H + r_a * 40 + ca + 8) = pa1; \
        *(uint4*)(Bs + (st) * BS_H + r_b * 136 + cb) = pb0; \
        *(uint4*)(Bs + (st) * BS_H + r_b * 136 + cb + 8) = pb1; \
    } while (0)

    wmma::fragment<wmma::accumulator, 16, 16, 16, float> cf[2][4];
    #pragma unroll
    for (int i = 0; i < 2; i++)
        #pragma unroll
        for (int j = 0; j < 4; j++) wmma::fill_fragment(cf[i][j], 0.f);

    LOAD_A(0); LOAD_B(0);
    STS(0);
    __syncthreads();

    #pragma unroll
    for (int t = 0; t < 4; t++) {
        if (t < 3) { LOAD_A((t + 1) * 32); LOAD_B((t + 1) * 32); }
        const int st = t & 1;
        #pragma unroll
        for (int ks = 0; ks < 2; ks++) {
            wmma::fragment<wmma::matrix_a, 16, 16, 16, __half, wmma::row_major> af0, af1;
            wmma::load_matrix_sync(af0, As + st * AS_H + (wm * 32) * 40 + ks * 16, 40);
            wmma::load_matrix_sync(af1, As + st * AS_H + (wm * 32 + 16) * 40 + ks * 16, 40);
            #pragma unroll
            for (int j = 0; j < 4; j++) {
                wmma::fragment<wmma::matrix_b, 16, 16, 16, __half, wmma::row_major> bf;
                wmma::load_matrix_sync(bf, Bs + st * BS_H + (ks * 16) * 136 + wn * 64 + j * 16, 136);
                wmma::mma_sync(cf[0][j], af0, bf, cf[0][j]);
                wmma::mma_sync(cf[1][j], af1, bf, cf[1][j]);
            }
        }
        if (t < 3) {
            __syncthreads();
            STS((t + 1) & 1);
            __syncthreads();
        }
    }

    /* epilogue: two phases through smem (Cs reuses As/Bs) */
    const int r = tid >> 1;
    const int gm = bm + r;
    const int head = blockIdx.x;                     /* valid for N=512 x-GEMM */
    float ds = 0.f, dd = 0.f;

    #pragma unroll
    for (int ph = 0; ph < 2; ph++) {
        __syncthreads();
        #pragma unroll
        for (int i = 0; i < 2; i++)
            #pragma unroll
            for (int q = 0; q < 2; q++)
                wmma::store_matrix_sync(Cs + (wm * 32 + i * 16) * 72 + wn * 32 + q * 16,
                                        cf[i][ph * 2 + q], 72, wmma::mem_row_major);
        __syncthreads();
        int c0 = (tid & 1) * 32;
        if (gm < M) {
            const float* srow = Cs + r * 72 + c0;
            int colb = (c0 ? 64 : 0) + ph * 32;      /* column within 128 */
            int gnb = bn + colb;
            #pragma unroll
            for (int c = 0; c < 32; c += 4) {
                float4 v = *(const float4*)(srow + c);
                if (bias) {
                    v.x += bias[gnb + c + 0];
                    v.y += bias[gnb + c + 1];
                    v.z += bias[gnb + c + 2];
                    v.w += bias[gnb + c + 3];
                }
                if (av) {
                    float4 a4 = *(const float4*)(av + head * D + colb + c);
                    float4 b4 = *(const float4*)(dv + head * D + colb + c);
                    ds += v.x * a4.x + v.y * a4.y + v.z * a4.z + v.w * a4.w;
                    dd += v.x * b4.x + v.y * b4.y + v.z * b4.z + v.w * b4.w;
                }
                if (sizeof(OutT) == 4) {
                    *(float4*)((float*)C + (long)gm * N + gnb + c) = v;
                } else {
                    __half2 h0 = __floats2half2_rn(v.x, v.y);
                    __half2 h1 = __floats2half2_rn(v.z, v.w);
                    uint2 u; u.x = *(unsigned*)&h0; u.y = *(unsigned*)&h1;
                    *(uint2*)((__half*)C + (long)gm * N + gnb + c) = u;
                }
            }
        }
    }
    /* warp-uniform shuffle: executed by ALL lanes (av is uniform) */
    if (av) {
        ds += __shfl_xor_sync(0xffffffffu, ds, 1);
        dd += __shfl_xor_sync(0xffffffffu, dd, 1);
        if (gm < M && !(tid & 1)) {
            als_out[(long)gm * NH + head] = ds;
            ald_out[(long)gm * NH + head] = dd;
        }
    }
    #undef LOAD_A
    #undef LOAD_B
    #undef STS
}

/* ---------------- LayerNorm + FiLM (fp16 output) ---------------- */
__global__ void k_ln_film(const float* __restrict__ ls, const float* __restrict__ lb,
                          const float* __restrict__ gam, const float* __restrict__ bet) {
    int n = (blockIdx.x * blockDim.x + threadIdx.x) >> 5;
    int lane = threadIdx.x & 31;
    if (n >= NN) return;
    float4 v = *(const float4*)(g_h + n * D + lane * 4);
    float mu = wredsum(v.x + v.y + v.z + v.w) * (1.f / 128.f);
    float d0 = v.x - mu, d1 = v.y - mu, d2 = v.z - mu, d3 = v.w - mu;
    float var = wredsum(d0 * d0 + d1 * d1 + d2 * d2 + d3 * d3) * (1.f / 128.f);
    float rs = rsqrtf(var + 1e-5f);
    float4 lsv = *(const float4*)(ls + lane * 4);
    float4 lbv = *(const float4*)(lb + lane * 4);
    float4 gv = *(const float4*)(gam + lane * 4);
    float4 bv = *(const float4*)(bet + lane * 4);
    float o0 = gv.x * (d0 * rs * lsv.x + lbv.x) + bv.x;
    float o1 = gv.y * (d1 * rs * lsv.y + lbv.y) + bv.y;
    float o2 = gv.z * (d2 * rs * lsv.z + lbv.z) + bv.z;
    float o3 = gv.w * (d3 * rs * lsv.w + lbv.w) + bv.w;
    __half2 h0 = __floats2half2_rn(o0, o1);
    __half2 h1 = __floats2half2_rn(o2, o3);
    uint2 u; u.x = *(unsigned*)&h0; u.y = *(unsigned*)&h1;
    *(uint2*)(g_hm + n * D + lane * 4) = u;
}

/* ---------------- edge attention vectors: warp per output ---------------- */
__global__ void k_attvec(const float* __restrict__ gWe, const float* __restrict__ gaedge) {
    int gw = blockIdx.x * 8 + (threadIdx.x >> 5);   /* 0 .. NL*128-1 */
    int lane = threadIdx.x & 31;
    int l = gw >> 7;
    int o = gw & 127;
    int h = o >> 5, f = o & 31;
    const float* We = gWe + (long)l * EFD * NH * D + (long)f * (NH * D) + h * D;
    const float* ae = gaedge + (long)l * NH * D + h * D;
    float4 w4 = *(const float4*)(We + lane * 4);
    float4 a4 = *(const float4*)(ae + lane * 4);
    float s = wredsum(w4.x * a4.x + w4.y * a4.y + w4.z * a4.z + w4.w * a4.w);
    if (lane == 0) g_v[l * NH * EFD + h * EFD + f] = s;
}
__global__ void k_aleself() {
    int l = blockIdx.x;
    int h = threadIdx.x >> 5, lane = threadIdx.x & 31;
    float s = wredsum(g_eamean[lane] * g_v[l * NH * EFD + h * EFD + lane]);
    if (lane == 0) g_aleself[l * NH + h] = s;
}

/* ---------------- per-edge attention logit al_e for ALL layers -------------- */
__global__ void k_ale_all(const float* __restrict__ ea) {
    __shared__ float sv[NL * NH * EFD];   /* 768 floats */
    __shared__ float se[128 * 33];
    int t = threadIdx.x;           /* 128 */
    long base = (long)blockIdx.x * 128;
    for (int i = t; i < NL * NH * EFD; i += 128) sv[i] = g_v[i];
    #pragma unroll
    for (int i = 0; i < 32; i++) {
        long li = (long)t + (long)i * 128;
        long gi = base * EFD + li;
        if (gi < (long)NE * EFD) {
            int row = (int)(li >> 5), col = (int)(li & 31);
            se[row * 33 + col] = ea[gi];
        }
    }
    __syncthreads();
    long j = base + t;
    if (j >= NE) return;
    float ev[EFD];
    #pragma unroll
    for (int k = 0; k < EFD; k++) ev[k] = se[t * 33 + k];
    #pragma unroll
    for (int l = 0; l < NL; l++) {
        float s0 = 0.f, s1 = 0.f, s2 = 0.f, s3 = 0.f;
        const float* v = sv + l * NH * EFD;
        #pragma unroll
        for (int k = 0; k < EFD; k++) {
            float e = ev[k];
            s0 += e * v[k];
            s1 += e * v[EFD + k];
            s2 += e * v[2 * EFD + k];
            s3 += e * v[3 * EFD + k];
        }
        float* o = g_ale + ((long)l * NE + j) * NH;
        o[0] = s0; o[1] = s1; o[2] = s2; o[3] = s3;
    }
}

/* ---------------- fused attention: softmax + gather in ONE kernel ----------- */
__global__ void k_attn(const float* __restrict__ ale_l,
                       const float* __restrict__ aleself_l,
                       const float* __restrict__ bias) {
    int n = (blockIdx.x * blockDim.x + threadIdx.x) >> 5;
    int lane = threadIdx.x & 31;
    if (n >= NN) return;
    int rb = g_rowptr[n], re = g_rowptr[n + 1];
    float4 ad = *(const float4*)(g_ald + (long)n * NH);

    float4 lw[4];
    int sreg[4];
    float4 mx = make_float4(-1e30f, -1e30f, -1e30f, -1e30f);
    #pragma unroll
    for (int j = 0; j < 4; j++) {
        int i = rb + lane + j * 32;
        lw[j] = make_float4(-1e30f, -1e30f, -1e30f, -1e30f);
        sreg[j] = 0;
        if (i < re) {
            int s = g_csrsrc[i], e = g_csreid[i];
            sreg[j] = s;
            float4 as = *(const float4*)(g_als + (long)s * NH);
            float4 ae = (e < NE) ? *(const float4*)(ale_l + (long)e * NH)
                                 : *(const float4*)aleself_l;
            float4 a; float t;
            t = as.x + ad.x + ae.x; a.x = t > 0.f ? t : 0.2f * t;
            t = as.y + ad.y + ae.y; a.y = t > 0.f ? t : 0.2f * t;
            t = as.z + ad.z + ae.z; a.z = t > 0.f ? t : 0.2f * t;
            t = as.w + ad.w + ae.w; a.w = t > 0.f ? t : 0.2f * t;
            lw[j] = a;
            mx.x = fmaxf(mx.x, a.x); mx.y = fmaxf(mx.y, a.y);
            mx.z = fmaxf(mx.z, a.z); mx.w = fmaxf(mx.w, a.w);
        }
    }
    for (int i = rb + lane + 128; i < re; i += 32) {   /* rare deg>128 spill */
        int s = g_csrsrc[i], e = g_csreid[i];
        float4 as = *(const float4*)(g_als + (long)s * NH);
        float4 ae = (e < NE) ? *(const float4*)(ale_l + (long)e * NH)
                             : *(const float4*)aleself_l;
        float4 a; float t;
        t = as.x + ad.x + ae.x; a.x = t > 0.f ? t : 0.2f * t;
        t = as.y + ad.y + ae.y; a.y = t > 0.f ? t : 0.2f * t;
        t = as.z + ad.z + ae.z; a.z = t > 0.f ? t : 0.2f * t;
        t = as.w + ad.w + ae.w; a.w = t > 0.f ? t : 0.2f * t;
        *(float4*)(g_lg + (long)i * NH) = a;
        mx.x = fmaxf(mx.x, a.x); mx.y = fmaxf(mx.y, a.y);
        mx.z = fmaxf(mx.z, a.z); mx.w = fmaxf(mx.w, a.w);
    }
    wredmax4(mx);

    float4 den = make_float4(0.f, 0.f, 0.f, 0.f);
    #pragma unroll
    for (int j = 0; j < 4; j++) {
        bool valid = (rb + lane + j * 32) < re;
        float4 a = lw[j];
        a.x = valid ? __expf(a.x - mx.x) : 0.f;
        a.y = valid ? __expf(a.y - mx.y) : 0.f;
        a.z = valid ? __expf(a.z - mx.z) : 0.f;
        a.w = valid ? __expf(a.w - mx.w) : 0.f;
        lw[j] = a;
        den.x += a.x; den.y += a.y; den.z += a.z; den.w += a.w;
    }
    for (int i = rb + lane + 128; i < re; i += 32) {
        float4 a = *(const float4*)(g_lg + (long)i * NH);
        a.x = __expf(a.x - mx.x); a.y = __expf(a.y - mx.y);
        a.z = __expf(a.z - mx.z); a.w = __expf(a.w - mx.w);
        *(float4*)(g_lg + (long)i * NH) = a;
        den.x += a.x; den.y += a.y; den.z += a.z; den.w += a.w;
    }
    wredsum4(den);
    float4 scl;
    scl.x = 0.25f / (den.x + 1e-16f);
    scl.y = 0.25f / (den.y + 1e-16f);
    scl.z = 0.25f / (den.z + 1e-16f);
    scl.w = 0.25f / (den.w + 1e-16f);

    #pragma unroll
    for (int j = 0; j < 4; j++) {
        int i = rb + lane + j * 32;
        if (i < re) {
            float4 o;
            o.x = lw[j].x * scl.x; o.y = lw[j].y * scl.y;
            o.z = lw[j].z * scl.z; o.w = lw[j].w * scl.w;
            *(float4*)(g_lg + (long)i * NH) = o;
        }
    }
    for (int i = rb + lane + 128; i < re; i += 32) {
        float4 a = *(const float4*)(g_lg + (long)i * NH);
        a.x *= scl.x; a.y *= scl.y; a.z *= scl.z; a.w *= scl.w;
        *(float4*)(g_lg + (long)i * NH) = a;
    }

    __syncwarp();   /* order g_lg writes before same-warp reads below */

    /* ---- pass B: weighted gather ---- */
    const int hh = lane >> 3;
    const int dp = (lane & 7) << 4;
    float acc[16];
    #pragma unroll
    for (int k = 0; k < 16; k++) acc[k] = 0.f;

    for (int i = rb; i < re; i++) {
        int rel = i - rb;
        int s;
        if (rel < 128) {
            int slot = rel >> 5;
            s = __shfl_sync(0xffffffffu, slot == 0 ? sreg[0] :
                            slot == 1 ? sreg[1] : slot == 2 ? sreg[2] : sreg[3],
                            rel & 31);
        } else {
            s = g_csrsrc[i];
        }
        float w = g_lg[(long)i * NH + hh];
        const __half* xp = g_x + (((long)s * NH + hh) << 7) + dp;
        uint4 r0 = *(const uint4*)xp;
        uint4 r1 = *(const uint4*)(xp + 8);
        const __half2* hp0 = (const __half2*)&r0;
        const __half2* hp1 = (const __half2*)&r1;
        #pragma unroll
        for (int q = 0; q < 4; q++) {
            float2 f = __half22float2(hp0[q]);
            acc[q * 2 + 0] += w * f.x;
            acc[q * 2 + 1] += w * f.y;
        }
        #pragma unroll
        for (int q = 0; q < 4; q++) {
            float2 f = __half22float2(hp1[q]);
            acc[8 + q * 2 + 0] += w * f.x;
            acc[8 + q * 2 + 1] += w * f.y;
        }
    }
    #pragma unroll
    for (int k = 0; k < 16; k++) {
        float vv = acc[k];
        vv += __shfl_xor_sync(0xffffffffu, vv, 8);
        vv += __shfl_xor_sync(0xffffffffu, vv, 16);
        acc[k] = vv;
    }
    if (lane < 8) {
        #pragma unroll
        for (int k = 0; k < 4; k++) {
            float4 o;
            o.x = fmaxf(acc[k * 4 + 0] + bias[dp + k * 4 + 0], 0.f);
            o.y = fmaxf(acc[k * 4 + 1] + bias[dp + k * 4 + 1], 0.f);
            o.z = fmaxf(acc[k * 4 + 2] + bias[dp + k * 4 + 2], 0.f);
            o.w = fmaxf(acc[k * 4 + 3] + bias[dp + k * 4 + 3], 0.f);
            *(float4*)(g_h + n * D + dp + k * 4) = o;
        }
    }
}

/* ---------------- fused edge head ---------------- */
__global__ void __launch_bounds__(256)
k_edge_head(const int* __restrict__ src, const int* __restrict__ dst,
            const float* __restrict__ W1, const float* __restrict__ b1,
            const float* __restrict__ W2, const float* __restrict__ b2,
            const float* __restrict__ ea, float* __restrict__ out) {
    __shared__ float sW[EFD][128];
    __shared__ float sb[128], sw2[128];
    int tid = threadIdx.x;
    for (int i = tid; i < EFD * 128; i += 256) sW[i >> 7][i & 127] = W1[256 * 128 + i];
    if (tid < 128) { sb[tid] = b1[tid]; sw2[tid] = W2[tid]; }
    __syncthreads();
    float bias2 = b2[0];
    int lane = tid & 31;
    int warp = blockIdx.x * 8 + (tid >> 5);
    int nwarps = gridDim.x * 8;
    const int NG = NE / 4;
    for (int g = warp; g < NG; g += nwarps) {
        int e = g * 4;
        float ev[4];
        float4 tu[4];
        #pragma unroll
        for (int k = 0; k < 4; k++) {
            int s = src[e + k], d = dst[e + k];
            ev[k] = ea[(long)(e + k) * EFD + lane];
            float4 tv = *(const float4*)(g_t + (long)s * D + lane * 4);
            float4 uv = *(const float4*)(g_u + (long)d * D + lane * 4);
            tu[k].x = tv.x + uv.x; tu[k].y = tv.y + uv.y;
            tu[k].z = tv.z + uv.z; tu[k].w = tv.w + uv.w;
        }
        float4 p[4];
        #pragma unroll
        for (int k = 0; k < 4; k++) p[k] = make_float4(0.f, 0.f, 0.f, 0.f);
        #pragma unroll
        for (int j = 0; j < EFD; j++) {
            float4 w = *(const float4*)&sW[j][lane * 4];
            #pragma unroll
            for (int k = 0; k < 4; k++) {
                float bj = __shfl_sync(0xffffffffu, ev[k], j);
                p[k].x += bj * w.x; p[k].y += bj * w.y;
                p[k].z += bj * w.z; p[k].w += bj * w.w;
            }
        }
        float4 bb = *(const float4*)&sb[lane * 4];
        float4 w2 = *(const float4*)&sw2[lane * 4];
        #pragma unroll
        for (int k = 0; k < 4; k++) {
            float z0 = fmaxf(tu[k].x + p[k].x + bb.x, 0.f);
            float z1 = fmaxf(tu[k].y + p[k].y + bb.y, 0.f);
            float z2 = fmaxf(tu[k].z + p[k].z + bb.z, 0.f);
            float z3 = fmaxf(tu[k].w + p[k].w + bb.w, 0.f);
            float s4 = wredsum(z0 * w2.x + z1 * w2.y + z2 * w2.z + z3 * w2.w);
            if (lane == 0) out[e + k] = s4 + bias2;
        }
    }
}

/* ---------------- host orchestration ---------------- */
extern "C" void kernel_launch(void* const* d_in, const int* in_sizes, int n_in,
                              void* d_out, int out_size) {
    const float* x      = (const float*)d_in[0];
    const int*   ei     = (const int*)  d_in[1];
    const float* ea     = (const float*)d_in[2];
    const float* gamma  = (const float*)d_in[3];
    const float* beta   = (const float*)d_in[4];
    const float* embW   = (const float*)d_in[5];
    const float* embb   = (const float*)d_in[6];
    const float* lns    = (const float*)d_in[7];
    const float* lnb    = (const float*)d_in[8];
    const float* gatW   = (const float*)d_in[9];
    const float* asrc   = (const float*)d_in[10];
    const float* adst   = (const float*)d_in[11];
    const float* gWe    = (const float*)d_in[12];
    const float* aedge  = (const float*)d_in[13];
    const float* gbias  = (const float*)d_in[14];
    const float* W1     = (const float*)d_in[15];
    const float* b1     = (const float*)d_in[16];
    const float* W2     = (const float*)d_in[17];
    const float* b2     = (const float*)d_in[18];
    float* out = (float*)d_out;

    const int* src = ei;
    const int* dst = ei + NE;

    float *p_h, *p_t, *p_u, *p_ale, *p_aleself, *p_als, *p_ald;
    __half *p_x, *p_hm, *p_xh, *p_wh, *p_ewh, *p_w1h;
    cudaGetSymbolAddress((void**)&p_h,  g_h);
    cudaGetSymbolAddress((void**)&p_hm, g_hm);
    cudaGetSymbolAddress((void**)&p_x,  g_x);
    cudaGetSymbolAddress((void**)&p_xh, g_xh);
    cudaGetSymbolAddress((void**)&p_wh, g_wh);
    cudaGetSymbolAddress((void**)&p_ewh, g_ewh);
    cudaGetSymbolAddress((void**)&p_w1h, g_w1h);
    cudaGetSymbolAddress((void**)&p_t,  g_t);
    cudaGetSymbolAddress((void**)&p_u,  g_u);
    cudaGetSymbolAddress((void**)&p_ale, g_ale);
    cudaGetSymbolAddress((void**)&p_aleself, g_aleself);
    cudaGetSymbolAddress((void**)&p_als, g_als);
    cudaGetSymbolAddress((void**)&p_ald, g_ald);

    const int MB = (NN + 127) / 128;   /* 196 */

    /* fp16 pre-conversions */
    k_f2h<<<(NN * D / 4 + 255) / 256, 256>>>(x, p_xh, NN * D);
    k_f2h<<<(D * D / 4 + 255) / 256, 256>>>(embW, p_ewh, D * D);
    k_f2h<<<(NL * D * NH * D / 4 + 255) / 256, 256>>>(gatW, p_wh, NL * D * NH * D);

    /* launch #4: embed GEMM (ncu -s 5 lands here) */
    k_gemm_mma<float><<<dim3(1, MB), 256>>>(p_xh, p_ewh, p_h, NN, 128, embb,
                                            (const float*)0, (const float*)0,
                                            (float*)0, (float*)0, (float*)0);

    k_f2h<<<(2 * D * D / 4 + 255) / 256, 256>>>(W1, p_w1h, 2 * D * D);

    /* CSR build */
    k_init_counts<<<(NN + 255) / 256, 256>>>();
    k_count<<<(NE + 255) / 256, 256>>>(dst);
    int nb = (NN + 1023) / 1024;
    k_scan_local<<<nb, 1024>>>();
    k_scan_fixup<<<1, 32>>>(nb);
    k_scan_add<<<(NN + 255) / 256, 256>>>();
    k_scatter_edges<<<(NE + 255) / 256, 256>>>(src, dst);
    k_scatter_self<<<(NN + 255) / 256, 256>>>();

    /* constants */
    k_eamean1<<<256, 128>>>(ea);
    k_eamean2<<<1, 32>>>();
    k_attvec<<<NL * 16, 256>>>(gWe, aedge);
    k_aleself<<<NL, 128>>>();
    k_ale_all<<<(NE + 127) / 128, 128>>>(ea);

    /* layers */
    for (int l = 0; l < NL; l++) {
        k_ln_film<<<(NN * 32 + 255) / 256, 256>>>(lns + l * D, lnb + l * D,
                                                  gamma + l * D, beta + l * D);
        k_gemm_mma<__half><<<dim3(4, MB), 256>>>(p_hm, p_wh + (long)l * D * NH * D,
                                                 p_x, NN, 512, (const float*)0,
                                                 asrc + l * NH * D, adst + l * NH * D,
                                                 p_als, p_ald, (__half*)0);
        k_attn<<<(NN * 32 + 255) / 256, 256>>>(p_ale + (long)l * NE * NH,
                                               p_aleself + l * NH,
                                               gbias + l * D);
    }

    /* head: convert h to fp16 (reuse g_xh), dual-output GEMM, edge head */
    k_f2h<<<(NN * D / 4 + 255) / 256, 256>>>(p_h, p_xh, NN * D);
    k_gemm_mma<float><<<dim3(2, MB), 256>>>(p_xh, p_w1h, p_t, NN, 128, (const float*)0,
                                            (const float*)0, (const float*)0,
                                            (float*)0, (float*)0, p_u);
    k_edge_head<<<2048, 256>>>(src, dst, W1, b1, W2, b2, ea, out);
}

// round 16
// speedup vs baseline: 1.0951x; 1.0054x over previous
#include <cuda_runtime.h>
#include <cuda_fp16.h>
#include <mma.h>

using namespace nvcuda;

#define NN  25000
#define NE  400000
#define NEF 425000   /* NE + NN self-loops */
#define D   128
#define NH  4
#define EFD 32
#define NL  6

/* ---------------- scratch (static device globals; no allocs) -------------- */
__device__ __align__(16) float  g_h[NN * D];
__device__ __align__(16) __half g_hm[NN * D];          /* LN output, fp16 */
__device__ __align__(16) __half g_xh[NN * D];          /* fp16 x / fp16 h for head */
__device__ __align__(16) __half g_x[NN * NH * D];
__device__ __align__(16) __half g_wh[NL * D * NH * D]; /* gatW fp16 */
__device__ __align__(16) __half g_ewh[D * D];          /* embW fp16 */
__device__ __align__(16) __half g_w1h[2 * D * D];      /* W1 t/u slices fp16 */
__device__ __align__(16) float  g_als[NN * NH];
__device__ __align__(16) float  g_ald[NN * NH];
__device__ __align__(16) float  g_ale[NL * NE * NH];
__device__ __align__(16) float  g_lg[NEF * NH];
__device__ int   g_rowptr[NN + 1];
__device__ int   g_counts[NN];
__device__ int   g_fill[NN];
__device__ int   g_csrsrc[NEF];
__device__ int   g_csreid[NEF];
__device__ __align__(16) float g_eamean[EFD];
__device__ __align__(16) float g_partial[256 * EFD];
__device__ __align__(16) float g_v[NL * NH * EFD];
__device__ __align__(16) float g_aleself[NL * NH];
__device__ __align__(16) float g_t[NN * D];
__device__ __align__(16) float g_u[NN * D];
__device__ int   g_bsums[32];

/* ---------------- helpers ---------------- */
__device__ __forceinline__ float wredsum(float v) {
    #pragma unroll
    for (int o = 16; o; o >>= 1) v += __shfl_xor_sync(0xffffffffu, v, o);
    return v;
}
__device__ __forceinline__ void wredsum4(float4& v) {
    #pragma unroll
    for (int o = 16; o; o >>= 1) {
        v.x += __shfl_xor_sync(0xffffffffu, v.x, o);
        v.y += __shfl_xor_sync(0xffffffffu, v.y, o);
        v.z += __shfl_xor_sync(0xffffffffu, v.z, o);
        v.w += __shfl_xor_sync(0xffffffffu, v.w, o);
    }
}
__device__ __forceinline__ void wredmax4(float4& v) {
    #pragma unroll
    for (int o = 16; o; o >>= 1) {
        v.x = fmaxf(v.x, __shfl_xor_sync(0xffffffffu, v.x, o));
        v.y = fmaxf(v.y, __shfl_xor_sync(0xffffffffu, v.y, o));
        v.z = fmaxf(v.z, __shfl_xor_sync(0xffffffffu, v.z, o));
        v.w = fmaxf(v.w, __shfl_xor_sync(0xffffffffu, v.w, o));
    }
}

/* ---------------- fp32 -> fp16 bulk convert ---------------- */
__global__ void k_f2h(const float* __restrict__ src, __half* __restrict__ dst, int n) {
    int i = (blockIdx.x * blockDim.x + threadIdx.x) * 4;
    if (i < n) {
        float4 v = *(const float4*)(src + i);
        __half2 h0 = __floats2half2_rn(v.x, v.y);
        __half2 h1 = __floats2half2_rn(v.z, v.w);
        uint2 u; u.x = *(unsigned*)&h0; u.y = *(unsigned*)&h1;
        *(uint2*)(dst + i) = u;
    }
}

/* ---------------- edge-attr mean (deterministic 2-stage) ---------------- */
__global__ void k_eamean1(const float* __restrict__ ea) {
    const int SPAN = 1563;
    int blk = blockIdx.x;
    int w = threadIdx.x >> 5, lane = threadIdx.x & 31;
    long start = (long)blk * SPAN;
    long end = start + SPAN; if (end > NE) end = NE;
    float s = 0.f;
    for (long e = start + w; e < end; e += 4) s += ea[e * EFD + lane];
    __shared__ float sm[4][32];
    sm[w][lane] = s;
    __syncthreads();
    if (w == 0) {
        float t = sm[0][lane] + sm[1][lane] + sm[2][lane] + sm[3][lane];
        g_partial[blk * 32 + lane] = t;
    }
}
__global__ void k_eamean2() {
    int lane = threadIdx.x;
    float s = 0.f;
    for (int b = 0; b < 256; b++) s += g_partial[b * 32 + lane];
    g_eamean[lane] = s * (1.f / (float)NE);
}

/* ---------------- CSR build ---------------- */
__global__ void k_init_counts() {
    int i = blockIdx.x * blockDim.x + threadIdx.x;
    if (i < NN) g_counts[i] = 1;   /* self loop */
}
__global__ void k_count(const int* __restrict__ dst) {
    int e = blockIdx.x * blockDim.x + threadIdx.x;
    if (e < NE) atomicAdd(&g_counts[dst[e]], 1);
}
__global__ void k_scan_local() {
    __shared__ int sm[1024];
    int base = blockIdx.x * 1024;
    int t = threadIdx.x;
    int v = (base + t < NN) ? g_counts[base + t] : 0;
    sm[t] = v;
    __syncthreads();
    #pragma unroll
    for (int off = 1; off < 1024; off <<= 1) {
        int x = (t >= off) ? sm[t - off] : 0;
        __syncthreads();
        sm[t] += x;
        __syncthreads();
    }
    if (base + t < NN) g_rowptr[base + t] = sm[t] - v;   /* exclusive */
    if (t == 1023) g_bsums[blockIdx.x] = sm[1023];
}
__global__ void k_scan_fixup(int nb) {
    int lane = threadIdx.x;                 /* 32 threads; nb <= 32 */
    int v = (lane < nb) ? g_bsums[lane] : 0;
    int orig = v;
    #pragma unroll
    for (int off = 1; off < 32; off <<= 1) {
        int x = __shfl_up_sync(0xffffffffu, v, off);
        if (lane >= off) v += x;
    }
    if (lane < nb) g_bsums[lane] = v - orig;   /* exclusive */
    if (lane == 31) g_rowptr[NN] = v;          /* total */
}
__global__ void k_scan_add() {
    int i = blockIdx.x * blockDim.x + threadIdx.x;
    if (i < NN) {
        int r = g_rowptr[i] + g_bsums[i >> 10];
        g_rowptr[i] = r;
        g_fill[i] = r;
    }
}
__global__ void k_scatter_edges(const int* __restrict__ src, const int* __restrict__ dst) {
    int e = blockIdx.x * blockDim.x + threadIdx.x;
    if (e < NE) {
        int d = dst[e];
        int pos = atomicAdd(&g_fill[d], 1);
        g_csrsrc[pos] = src[e];
        g_csreid[pos] = e;
    }
}
__global__ void k_scatter_self() {
    int i = blockIdx.x * blockDim.x + threadIdx.x;
    if (i < NN) {
        int pos = atomicAdd(&g_fill[i], 1);
        g_csrsrc[pos] = i;
        g_csreid[pos] = NE + i;
    }
}

/* ================= tensor-core GEMM: C[M,N] = A[M,128] @ B[128,N] =========
   R13-verified design: fp16 pre-converted operands, BK=32 double buffer,
   STATIC 37.9KB smem, 2 blocks/SM. Single-sync mainloop (STS targets the
   other buffer; end-of-iteration sync protects reuse). Optional fused
   attention dots (av/dv); optional dual-output mode (C2). */

#define AS_H 5120      /* halves per A stage: 128*40 */
#define BS_H 4352      /* halves per B stage: 32*136 */
#define SMEM_BYTES 37888

template <typename OutT>
__global__ void __launch_bounds__(256, 2)
k_gemm_mma(const __half* __restrict__ A, const __half* __restrict__ B,
           OutT* __restrict__ C, int M, int N, const float* __restrict__ bias,
           const float* __restrict__ av, const float* __restrict__ dv,
           float* __restrict__ als_out, float* __restrict__ ald_out,
           OutT* __restrict__ C2) {
    __shared__ __align__(16) char smem[SMEM_BYTES];
    __half* As = (__half*)smem;                 /* [2][128][40] */
    __half* Bs = (__half*)(smem + 20480);       /* [2][32][136] */
    float*  Cs = (float*)smem;                  /* [128][72] epilogue reuse */

    const int tid = threadIdx.x;
    const int bm = blockIdx.y * 128;
    const int bn = C2 ? 0 : blockIdx.x * 128;
    if (C2 && blockIdx.x == 1) { B += 128 * 128; C = C2; }
    const int warp = tid >> 5;
    const int wm = warp >> 1;      /* 0..3 */
    const int wn = warp & 1;       /* 0..1 */

    const int r_a = tid >> 1, ca = (tid & 1) * 16;
    const int r_b = tid >> 3, cb = (tid & 7) * 16;
    const bool arow_ok = (bm + r_a) < M;
    const __half* Aptr = A + (long)(bm + r_a) * 128 + ca;
    const __half* Bptr = B + (long)r_b * N + bn + cb;

    uint4 pa0, pa1, pb0, pb1;
    #define LOAD_A(kk) do { \
        if (arow_ok) { \
            pa0 = *(const uint4*)(Aptr + (kk)); \
            pa1 = *(const uint4*)(Aptr + (kk) + 8); \
        } else { pa0 = make_uint4(0,0,0,0); pa1 = pa0; } \
    } while (0)
    #define LOAD_B(kk) do { \
        const __half* bp = Bptr + (long)(kk) * N; \
        pb0 = *(const uint4*)bp; \
        pb1 = *(const uint4*)(bp + 8); \
    } while (0)
    #define STS(st) do { \
        *(uint4*)(As + (st) * AS_H + r_a * 40 + ca) = pa0; \
        *(uint4*)(As + (st) * AS_H + r_a * 40 + ca + 8) = pa1; \
        *(uint4*)(Bs + (st) * BS_H + r_b * 136 + cb) = pb0; \
        *(uint4*)(Bs + (st) * BS_H + r_b * 136 + cb + 8) = pb1; \
    } while (0)

    wmma::fragment<wmma::accumulator, 16, 16, 16, float> cf[2][4];
    #pragma unroll
    for (int i = 0; i < 2; i++)
        #pragma unroll
        for (int j = 0; j < 4; j++) wmma::fill_fragment(cf[i][j], 0.f);

    LOAD_A(0); LOAD_B(0);
    STS(0);
    __syncthreads();

    #pragma unroll
    for (int t = 0; t < 4; t++) {
        if (t < 3) { LOAD_A((t + 1) * 32); LOAD_B((t + 1) * 32); }
        const int st = t & 1;
        #pragma unroll
        for (int ks = 0; ks < 2; ks++) {
            wmma::fragment<wmma::matrix_a, 16, 16, 16, __half, wmma::row_major> af0, af1;
            wmma::load_matrix_sync(af0, As + st * AS_H + (wm * 32) * 40 + ks * 16, 40);
            wmma::load_matrix_sync(af1, As + st * AS_H + (wm * 32 + 16) * 40 + ks * 16, 40);
            #pragma unroll
            for (int j = 0; j < 4; j++) {
                wmma::fragment<wmma::matrix_b, 16, 16, 16, __half, wmma::row_major> bf;
                wmma::load_matrix_sync(bf, Bs + st * BS_H + (ks * 16) * 136 + wn * 64 + j * 16, 136);
                wmma::mma_sync(cf[0][j], af0, bf, cf[0][j]);
                wmma::mma_sync(cf[1][j], af1, bf, cf[1][j]);
            }
        }
        if (t < 3) {
            /* single sync: STS targets buffer st^1, whose readers finished
               before the sync that ended iteration t-1. */
            STS((t + 1) & 1);
            __syncthreads();
        }
    }

    /* epilogue: two phases through smem (Cs reuses As/Bs) */
    const int r = tid >> 1;
    const int gm = bm + r;
    const int head = blockIdx.x;                     /* valid for N=512 x-GEMM */
    float ds = 0.f, dd = 0.f;

    #pragma unroll
    for (int ph = 0; ph < 2; ph++) {
        __syncthreads();
        #pragma unroll
        for (int i = 0; i < 2; i++)
            #pragma unroll
            for (int q = 0; q < 2; q++)
                wmma::store_matrix_sync(Cs + (wm * 32 + i * 16) * 72 + wn * 32 + q * 16,
                                        cf[i][ph * 2 + q], 72, wmma::mem_row_major);
        __syncthreads();
        int c0 = (tid & 1) * 32;
        if (gm < M) {
            const float* srow = Cs + r * 72 + c0;
            int colb = (c0 ? 64 : 0) + ph * 32;      /* column within 128 */
            int gnb = bn + colb;
            #pragma unroll
            for (int c = 0; c < 32; c += 4) {
                float4 v = *(const float4*)(srow + c);
                if (bias) {
                    v.x += bias[gnb + c + 0];
                    v.y += bias[gnb + c + 1];
                    v.z += bias[gnb + c + 2];
                    v.w += bias[gnb + c + 3];
                }
                if (av) {
                    float4 a4 = *(const float4*)(av + head * D + colb + c);
                    float4 b4 = *(const float4*)(dv + head * D + colb + c);
                    ds += v.x * a4.x + v.y * a4.y + v.z * a4.z + v.w * a4.w;
                    dd += v.x * b4.x + v.y * b4.y + v.z * b4.z + v.w * b4.w;
                }
                if (sizeof(OutT) == 4) {
                    *(float4*)((float*)C + (long)gm * N + gnb + c) = v;
                } else {
                    __half2 h0 = __floats2half2_rn(v.x, v.y);
                    __half2 h1 = __floats2half2_rn(v.z, v.w);
                    uint2 u; u.x = *(unsigned*)&h0; u.y = *(unsigned*)&h1;
                    *(uint2*)((__half*)C + (long)gm * N + gnb + c) = u;
                }
            }
        }
    }
    /* warp-uniform shuffle: executed by ALL lanes (av is uniform) */
    if (av) {
        ds += __shfl_xor_sync(0xffffffffu, ds, 1);
        dd += __shfl_xor_sync(0xffffffffu, dd, 1);
        if (gm < M && !(tid & 1)) {
            als_out[(long)gm * NH + head] = ds;
            ald_out[(long)gm * NH + head] = dd;
        }
    }
    #undef LOAD_A
    #undef LOAD_B
    #undef STS
}

/* ---------------- LayerNorm + FiLM (fp16 output) ---------------- */
__global__ void k_ln_film(const float* __restrict__ ls, const float* __restrict__ lb,
                          const float* __restrict__ gam, const float* __restrict__ bet) {
    int n = (blockIdx.x * blockDim.x + threadIdx.x) >> 5;
    int lane = threadIdx.x & 31;
    if (n >= NN) return;
    float4 v = *(const float4*)(g_h + n * D + lane * 4);
    float mu = wredsum(v.x + v.y + v.z + v.w) * (1.f / 128.f);
    float d0 = v.x - mu, d1 = v.y - mu, d2 = v.z - mu, d3 = v.w - mu;
    float var = wredsum(d0 * d0 + d1 * d1 + d2 * d2 + d3 * d3) * (1.f / 128.f);
    float rs = rsqrtf(var + 1e-5f);
    float4 lsv = *(const float4*)(ls + lane * 4);
    float4 lbv = *(const float4*)(lb + lane * 4);
    float4 gv = *(const float4*)(gam + lane * 4);
    float4 bv = *(const float4*)(bet + lane * 4);
    float o0 = gv.x * (d0 * rs * lsv.x + lbv.x) + bv.x;
    float o1 = gv.y * (d1 * rs * lsv.y + lbv.y) + bv.y;
    float o2 = gv.z * (d2 * rs * lsv.z + lbv.z) + bv.z;
    float o3 = gv.w * (d3 * rs * lsv.w + lbv.w) + bv.w;
    __half2 h0 = __floats2half2_rn(o0, o1);
    __half2 h1 = __floats2half2_rn(o2, o3);
    uint2 u; u.x = *(unsigned*)&h0; u.y = *(unsigned*)&h1;
    *(uint2*)(g_hm + n * D + lane * 4) = u;
}

/* ---------------- edge attention vectors: warp per output ---------------- */
__global__ void k_attvec(const float* __restrict__ gWe, const float* __restrict__ gaedge) {
    int gw = blockIdx.x * 8 + (threadIdx.x >> 5);   /* 0 .. NL*128-1 */
    int lane = threadIdx.x & 31;
    int l = gw >> 7;
    int o = gw & 127;
    int h = o >> 5, f = o & 31;
    const float* We = gWe + (long)l * EFD * NH * D + (long)f * (NH * D) + h * D;
    const float* ae = gaedge + (long)l * NH * D + h * D;
    float4 w4 = *(const float4*)(We + lane * 4);
    float4 a4 = *(const float4*)(ae + lane * 4);
    float s = wredsum(w4.x * a4.x + w4.y * a4.y + w4.z * a4.z + w4.w * a4.w);
    if (lane == 0) g_v[l * NH * EFD + h * EFD + f] = s;
}
__global__ void k_aleself() {
    int l = blockIdx.x;
    int h = threadIdx.x >> 5, lane = threadIdx.x & 31;
    float s = wredsum(g_eamean[lane] * g_v[l * NH * EFD + h * EFD + lane]);
    if (lane == 0) g_aleself[l * NH + h] = s;
}

/* ---------------- per-edge attention logit al_e for ALL layers -------------- */
__global__ void k_ale_all(const float* __restrict__ ea) {
    __shared__ float sv[NL * NH * EFD];   /* 768 floats */
    __shared__ float se[128 * 33];
    int t = threadIdx.x;           /* 128 */
    long base = (long)blockIdx.x * 128;
    for (int i = t; i < NL * NH * EFD; i += 128) sv[i] = g_v[i];
    #pragma unroll
    for (int i = 0; i < 32; i++) {
        long li = (long)t + (long)i * 128;
        long gi = base * EFD + li;
        if (gi < (long)NE * EFD) {
            int row = (int)(li >> 5), col = (int)(li & 31);
            se[row * 33 + col] = ea[gi];
        }
    }
    __syncthreads();
    long j = base + t;
    if (j >= NE) return;
    float ev[EFD];
    #pragma unroll
    for (int k = 0; k < EFD; k++) ev[k] = se[t * 33 + k];
    #pragma unroll
    for (int l = 0; l < NL; l++) {
        float s0 = 0.f, s1 = 0.f, s2 = 0.f, s3 = 0.f;
        const float* v = sv + l * NH * EFD;
        #pragma unroll
        for (int k = 0; k < EFD; k++) {
            float e = ev[k];
            s0 += e * v[k];
            s1 += e * v[EFD + k];
            s2 += e * v[2 * EFD + k];
            s3 += e * v[3 * EFD + k];
        }
        float* o = g_ale + ((long)l * NE + j) * NH;
        o[0] = s0; o[1] = s1; o[2] = s2; o[3] = s3;
    }
}

/* ---------------- fused attention: softmax + gather in ONE kernel -----------
   Optional o16: fp16 copy of the output h (used before the head GEMM). */
__global__ void k_attn(const float* __restrict__ ale_l,
                       const float* __restrict__ aleself_l,
                       const float* __restrict__ bias,
                       __half* __restrict__ o16) {
    int n = (blockIdx.x * blockDim.x + threadIdx.x) >> 5;
    int lane = threadIdx.x & 31;
    if (n >= NN) return;
    int rb = g_rowptr[n], re = g_rowptr[n + 1];
    float4 ad = *(const float4*)(g_ald + (long)n * NH);

    float4 lw[4];
    int sreg[4];
    float4 mx = make_float4(-1e30f, -1e30f, -1e30f, -1e30f);
    #pragma unroll
    for (int j = 0; j < 4; j++) {
        int i = rb + lane + j * 32;
        lw[j] = make_float4(-1e30f, -1e30f, -1e30f, -1e30f);
        sreg[j] = 0;
        if (i < re) {
            int s = g_csrsrc[i], e = g_csreid[i];
            sreg[j] = s;
            float4 as = *(const float4*)(g_als + (long)s * NH);
            float4 ae = (e < NE) ? *(const float4*)(ale_l + (long)e * NH)
                                 : *(const float4*)aleself_l;
            float4 a; float t;
            t = as.x + ad.x + ae.x; a.x = t > 0.f ? t : 0.2f * t;
            t = as.y + ad.y + ae.y; a.y = t > 0.f ? t : 0.2f * t;
            t = as.z + ad.z + ae.z; a.z = t > 0.f ? t : 0.2f * t;
            t = as.w + ad.w + ae.w; a.w = t > 0.f ? t : 0.2f * t;
            lw[j] = a;
            mx.x = fmaxf(mx.x, a.x); mx.y = fmaxf(mx.y, a.y);
            mx.z = fmaxf(mx.z, a.z); mx.w = fmaxf(mx.w, a.w);
        }
    }
    for (int i = rb + lane + 128; i < re; i += 32) {   /* rare deg>128 spill */
        int s = g_csrsrc[i], e = g_csreid[i];
        float4 as = *(const float4*)(g_als + (long)s * NH);
        float4 ae = (e < NE) ? *(const float4*)(ale_l + (long)e * NH)
                             : *(const float4*)aleself_l;
        float4 a; float t;
        t = as.x + ad.x + ae.x; a.x = t > 0.f ? t : 0.2f * t;
        t = as.y + ad.y + ae.y; a.y = t > 0.f ? t : 0.2f * t;
        t = as.z + ad.z + ae.z; a.z = t > 0.f ? t : 0.2f * t;
        t = as.w + ad.w + ae.w; a.w = t > 0.f ? t : 0.2f * t;
        *(float4*)(g_lg + (long)i * NH) = a;
        mx.x = fmaxf(mx.x, a.x); mx.y = fmaxf(mx.y, a.y);
        mx.z = fmaxf(mx.z, a.z); mx.w = fmaxf(mx.w, a.w);
    }
    wredmax4(mx);

    float4 den = make_float4(0.f, 0.f, 0.f, 0.f);
    #pragma unroll
    for (int j = 0; j < 4; j++) {
        bool valid = (rb + lane + j * 32) < re;
        float4 a = lw[j];
        a.x = valid ? __expf(a.x - mx.x) : 0.f;
        a.y = valid ? __expf(a.y - mx.y) : 0.f;
        a.z = valid ? __expf(a.z - mx.z) : 0.f;
        a.w = valid ? __expf(a.w - mx.w) : 0.f;
        lw[j] = a;
        den.x += a.x; den.y += a.y; den.z += a.z; den.w += a.w;
    }
    for (int i = rb + lane + 128; i < re; i += 32) {
        float4 a = *(const float4*)(g_lg + (long)i * NH);
        a.x = __expf(a.x - mx.x); a.y = __expf(a.y - mx.y);
        a.z = __expf(a.z - mx.z); a.w = __expf(a.w - mx.w);
        *(float4*)(g_lg + (long)i * NH) = a;
        den.x += a.x; den.y += a.y; den.z += a.z; den.w += a.w;
    }
    wredsum4(den);
    float4 scl;
    scl.x = 0.25f / (den.x + 1e-16f);
    scl.y = 0.25f / (den.y + 1e-16f);
    scl.z = 0.25f / (den.z + 1e-16f);
    scl.w = 0.25f / (den.w + 1e-16f);

    #pragma unroll
    for (int j = 0; j < 4; j++) {
        int i = rb + lane + j * 32;
        if (i < re) {
            float4 o;
            o.x = lw[j].x * scl.x; o.y = lw[j].y * scl.y;
            o.z = lw[j].z * scl.z; o.w = lw[j].w * scl.w;
            *(float4*)(g_lg + (long)i * NH) = o;
        }
    }
    for (int i = rb + lane + 128; i < re; i += 32) {
        float4 a = *(const float4*)(g_lg + (long)i * NH);
        a.x *= scl.x; a.y *= scl.y; a.z *= scl.z; a.w *= scl.w;
        *(float4*)(g_lg + (long)i * NH) = a;
    }

    __syncwarp();   /* order g_lg writes before same-warp reads below */

    /* ---- pass B: weighted gather ---- */
    const int hh = lane >> 3;
    const int dp = (lane & 7) << 4;
    float acc[16];
    #pragma unroll
    for (int k = 0; k < 16; k++) acc[k] = 0.f;

    for (int i = rb; i < re; i++) {
        int rel = i - rb;
        int s;
        if (rel < 128) {
            int slot = rel >> 5;
            s = __shfl_sync(0xffffffffu, slot == 0 ? sreg[0] :
                            slot == 1 ? sreg[1] : slot == 2 ? sreg[2] : sreg[3],
                            rel & 31);
        } else {
            s = g_csrsrc[i];
        }
        float w = g_lg[(long)i * NH + hh];
        const __half* xp = g_x + (((long)s * NH + hh) << 7) + dp;
        uint4 r0 = *(const uint4*)xp;
        uint4 r1 = *(const uint4*)(xp + 8);
        const __half2* hp0 = (const __half2*)&r0;
        const __half2* hp1 = (const __half2*)&r1;
        #pragma unroll
        for (int q = 0; q < 4; q++) {
            float2 f = __half22float2(hp0[q]);
            acc[q * 2 + 0] += w * f.x;
            acc[q * 2 + 1] += w * f.y;
        }
        #pragma unroll
        for (int q = 0; q < 4; q++) {
            float2 f = __half22float2(hp1[q]);
            acc[8 + q * 2 + 0] += w * f.x;
            acc[8 + q * 2 + 1] += w * f.y;
        }
    }
    #pragma unroll
    for (int k = 0; k < 16; k++) {
        float vv = acc[k];
        vv += __shfl_xor_sync(0xffffffffu, vv, 8);
        vv += __shfl_xor_sync(0xffffffffu, vv, 16);
        acc[k] = vv;
    }
    if (lane < 8) {
        float ov[16];
        #pragma unroll
        for (int k = 0; k < 4; k++) {
            float4 o;
            o.x = fmaxf(acc[k * 4 + 0] + bias[dp + k * 4 + 0], 0.f);
            o.y = fmaxf(acc[k * 4 + 1] + bias[dp + k * 4 + 1], 0.f);
            o.z = fmaxf(acc[k * 4 + 2] + bias[dp + k * 4 + 2], 0.f);
            o.w = fmaxf(acc[k * 4 + 3] + bias[dp + k * 4 + 3], 0.f);
            *(float4*)(g_h + n * D + dp + k * 4) = o;
            ov[k * 4 + 0] = o.x; ov[k * 4 + 1] = o.y;
            ov[k * 4 + 2] = o.z; ov[k * 4 + 3] = o.w;
        }
        if (o16) {
            __half2 hh2[8];
            #pragma unroll
            for (int q = 0; q < 8; q++)
                hh2[q] = __floats2half2_rn(ov[q * 2], ov[q * 2 + 1]);
            *(uint4*)(o16 + n * D + dp)     = *(const uint4*)&hh2[0];
            *(uint4*)(o16 + n * D + dp + 8) = *(const uint4*)&hh2[4];
        }
    }
}

/* ---------------- fused edge head ---------------- */
__global__ void __launch_bounds__(256)
k_edge_head(const int* __restrict__ src, const int* __restrict__ dst,
            const float* __restrict__ W1, const float* __restrict__ b1,
            const float* __restrict__ W2, const float* __restrict__ b2,
            const float* __restrict__ ea, float* __restrict__ out) {
    __shared__ float sW[EFD][128];
    __shared__ float sb[128], sw2[128];
    int tid = threadIdx.x;
    for (int i = tid; i < EFD * 128; i += 256) sW[i >> 7][i & 127] = W1[256 * 128 + i];
    if (tid < 128) { sb[tid] = b1[tid]; sw2[tid] = W2[tid]; }
    __syncthreads();
    float bias2 = b2[0];
    int lane = tid & 31;
    int warp = blockIdx.x * 8 + (tid >> 5);
    int nwarps = gridDim.x * 8;
    const int NG = NE / 4;
    for (int g = warp; g < NG; g += nwarps) {
        int e = g * 4;
        float ev[4];
        float4 tu[4];
        #pragma unroll
        for (int k = 0; k < 4; k++) {
            int s = src[e + k], d = dst[e + k];
            ev[k] = ea[(long)(e + k) * EFD + lane];
            float4 tv = *(const float4*)(g_t + (long)s * D + lane * 4);
            float4 uv = *(const float4*)(g_u + (long)d * D + lane * 4);
            tu[k].x = tv.x + uv.x; tu[k].y = tv.y + uv.y;
            tu[k].z = tv.z + uv.z; tu[k].w = tv.w + uv.w;
        }
        float4 p[4];
        #pragma unroll
        for (int k = 0; k < 4; k++) p[k] = make_float4(0.f, 0.f, 0.f, 0.f);
        #pragma unroll
        for (int j = 0; j < EFD; j++) {
            float4 w = *(const float4*)&sW[j][lane * 4];
            #pragma unroll
            for (int k = 0; k < 4; k++) {
                float bj = __shfl_sync(0xffffffffu, ev[k], j);
                p[k].x += bj * w.x; p[k].y += bj * w.y;
                p[k].z += bj * w.z; p[k].w += bj * w.w;
            }
        }
        float4 bb = *(const float4*)&sb[lane * 4];
        float4 w2 = *(const float4*)&sw2[lane * 4];
        #pragma unroll
        for (int k = 0; k < 4; k++) {
            float z0 = fmaxf(tu[k].x + p[k].x + bb.x, 0.f);
            float z1 = fmaxf(tu[k].y + p[k].y + bb.y, 0.f);
            float z2 = fmaxf(tu[k].z + p[k].z + bb.z, 0.f);
            float z3 = fmaxf(tu[k].w + p[k].w + bb.w, 0.f);
            float s4 = wredsum(z0 * w2.x + z1 * w2.y + z2 * w2.z + z3 * w2.w);
            if (lane == 0) out[e + k] = s4 + bias2;
        }
    }
}

/* ---------------- host orchestration ---------------- */
extern "C" void kernel_launch(void* const* d_in, const int* in_sizes, int n_in,
                              void* d_out, int out_size) {
    const float* x      = (const float*)d_in[0];
    const int*   ei     = (const int*)  d_in[1];
    const float* ea     = (const float*)d_in[2];
    const float* gamma  = (const float*)d_in[3];
    const float* beta   = (const float*)d_in[4];
    const float* embW   = (const float*)d_in[5];
    const float* embb   = (const float*)d_in[6];
    const float* lns    = (const float*)d_in[7];
    const float* lnb    = (const float*)d_in[8];
    const float* gatW   = (const float*)d_in[9];
    const float* asrc   = (const float*)d_in[10];
    const float* adst   = (const float*)d_in[11];
    const float* gWe    = (const float*)d_in[12];
    const float* aedge  = (const float*)d_in[13];
    const float* gbias  = (const float*)d_in[14];
    const float* W1     = (const float*)d_in[15];
    const float* b1     = (const float*)d_in[16];
    const float* W2     = (const float*)d_in[17];
    const float* b2     = (const float*)d_in[18];
    float* out = (float*)d_out;

    const int* src = ei;
    const int* dst = ei + NE;

    float *p_h, *p_t, *p_u, *p_ale, *p_aleself, *p_als, *p_ald;
    __half *p_x, *p_hm, *p_xh, *p_wh, *p_ewh, *p_w1h;
    cudaGetSymbolAddress((void**)&p_h,  g_h);
    cudaGetSymbolAddress((void**)&p_hm, g_hm);
    cudaGetSymbolAddress((void**)&p_x,  g_x);
    cudaGetSymbolAddress((void**)&p_xh, g_xh);
    cudaGetSymbolAddress((void**)&p_wh, g_wh);
    cudaGetSymbolAddress((void**)&p_ewh, g_ewh);
    cudaGetSymbolAddress((void**)&p_w1h, g_w1h);
    cudaGetSymbolAddress((void**)&p_t,  g_t);
    cudaGetSymbolAddress((void**)&p_u,  g_u);
    cudaGetSymbolAddress((void**)&p_ale, g_ale);
    cudaGetSymbolAddress((void**)&p_aleself, g_aleself);
    cudaGetSymbolAddress((void**)&p_als, g_als);
    cudaGetSymbolAddress((void**)&p_ald, g_ald);

    const int MB = (NN + 127) / 128;   /* 196 */

    /* fp16 pre-conversions */
    k_f2h<<<(NN * D / 4 + 255) / 256, 256>>>(x, p_xh, NN * D);
    k_f2h<<<(D * D / 4 + 255) / 256, 256>>>(embW, p_ewh, D * D);
    k_f2h<<<(NL * D * NH * D / 4 + 255) / 256, 256>>>(gatW, p_wh, NL * D * NH * D);

    /* launch #4: embed GEMM (ncu -s 5 lands here) */
    k_gemm_mma<float><<<dim3(1, MB), 256>>>(p_xh, p_ewh, p_h, NN, 128, embb,
                                            (const float*)0, (const float*)0,
                                            (float*)0, (float*)0, (float*)0);

    k_f2h<<<(2 * D * D / 4 + 255) / 256, 256>>>(W1, p_w1h, 2 * D * D);

    /* CSR build */
    k_init_counts<<<(NN + 255) / 256, 256>>>();
    k_count<<<(NE + 255) / 256, 256>>>(dst);
    int nb = (NN + 1023) / 1024;
    k_scan_local<<<nb, 1024>>>();
    k_scan_fixup<<<1, 32>>>(nb);
    k_scan_add<<<(NN + 255) / 256, 256>>>();
    k_scatter_edges<<<(NE + 255) / 256, 256>>>(src, dst);
    k_scatter_self<<<(NN + 255) / 256, 256>>>();

    /* constants */
    k_eamean1<<<256, 128>>>(ea);
    k_eamean2<<<1, 32>>>();
    k_attvec<<<NL * 16, 256>>>(gWe, aedge);
    k_aleself<<<NL, 128>>>();
    k_ale_all<<<(NE + 127) / 128, 128>>>(ea);

    /* layers; last layer's k_attn also emits fp16 h for the head GEMM */
    for (int l = 0; l < NL; l++) {
        k_ln_film<<<(NN * 32 + 255) / 256, 256>>>(lns + l * D, lnb + l * D,
                                                  gamma + l * D, beta + l * D);
        k_gemm_mma<__half><<<dim3(4, MB), 256>>>(p_hm, p_wh + (long)l * D * NH * D,
                                                 p_x, NN, 512, (const float*)0,
                                                 asrc + l * NH * D, adst + l * NH * D,
                                                 p_als, p_ald, (__half*)0);
        k_attn<<<(NN * 32 + 255) / 256, 256>>>(p_ale + (long)l * NE * NH,
                                               p_aleself + l * NH,
                                               gbias + l * D,
                                               (l == NL - 1) ? p_xh : (__half*)0);
    }

    /* head: dual-output GEMM (t and u in one launch), fused edge head */
    k_gemm_mma<float><<<dim3(2, MB), 256>>>(p_xh, p_w1h, p_t, NN, 128, (const float*)0,
                                            (const float*)0, (const float*)0,
                                            (float*)0, (float*)0, p_u);
    k_edge_head<<<2048, 256>>>(src, dst, W1, b1, W2, b2, ea, out);
}

// round 17
// speedup vs baseline: 1.1046x; 1.0087x over previous
#include <cuda_runtime.h>
#include <cuda_fp16.h>
#include <mma.h>

using namespace nvcuda;

#define NN  25000
#define NE  400000
#define NEF 425000   /* NE + NN self-loops */
#define D   128
#define NH  4
#define EFD 32
#define NL  6

/* ---------------- scratch (static device globals; no allocs) -------------- */
__device__ __align__(16) float  g_h[NN * D];           /* fp32 h (layer 0 only) */
__device__ __align__(16) __half g_hm[NN * D];          /* LN output, fp16 */
__device__ __align__(16) __half g_xh[NN * D];          /* fp16 x / fp16 h for head */
__device__ __align__(16) __half g_x[NN * NH * D];
__device__ __align__(16) __half g_wh[NL * D * NH * D]; /* gatW fp16 */
__device__ __align__(16) __half g_ewh[D * D];          /* embW fp16 */
__device__ __align__(16) __half g_w1h[2 * D * D];      /* W1 t/u slices fp16 */
__device__ __align__(16) float  g_als[NN * NH];
__device__ __align__(16) float  g_ald[NN * NH];
__device__ __align__(16) float  g_ale[NL * NE * NH];
__device__ __align__(16) float  g_lg[NEF * NH];
__device__ int   g_rowptr[NN + 1];
__device__ int   g_counts[NN];
__device__ int   g_fill[NN];
__device__ int   g_csrsrc[NEF];
__device__ int   g_csreid[NEF];
__device__ __align__(16) float g_eamean[EFD];
__device__ __align__(16) float g_partial[256 * EFD];
__device__ __align__(16) float g_v[NL * NH * EFD];
__device__ __align__(16) float g_aleself[NL * NH];
__device__ __align__(16) float g_t[NN * D];
__device__ __align__(16) float g_u[NN * D];
__device__ int   g_bsums[32];

/* ---------------- helpers ---------------- */
__device__ __forceinline__ float wredsum(float v) {
    #pragma unroll
    for (int o = 16; o; o >>= 1) v += __shfl_xor_sync(0xffffffffu, v, o);
    return v;
}
__device__ __forceinline__ void wredsum4(float4& v) {
    #pragma unroll
    for (int o = 16; o; o >>= 1) {
        v.x += __shfl_xor_sync(0xffffffffu, v.x, o);
        v.y += __shfl_xor_sync(0xffffffffu, v.y, o);
        v.z += __shfl_xor_sync(0xffffffffu, v.z, o);
        v.w += __shfl_xor_sync(0xffffffffu, v.w, o);
    }
}
__device__ __forceinline__ void wredmax4(float4& v) {
    #pragma unroll
    for (int o = 16; o; o >>= 1) {
        v.x = fmaxf(v.x, __shfl_xor_sync(0xffffffffu, v.x, o));
        v.y = fmaxf(v.y, __shfl_xor_sync(0xffffffffu, v.y, o));
        v.z = fmaxf(v.z, __shfl_xor_sync(0xffffffffu, v.z, o));
        v.w = fmaxf(v.w, __shfl_xor_sync(0xffffffffu, v.w, o));
    }
}

/* ---------------- fp32 -> fp16 bulk convert ---------------- */
__global__ void k_f2h(const float* __restrict__ src, __half* __restrict__ dst, int n) {
    int i = (blockIdx.x * blockDim.x + threadIdx.x) * 4;
    if (i < n) {
        float4 v = *(const float4*)(src + i);
        __half2 h0 = __floats2half2_rn(v.x, v.y);
        __half2 h1 = __floats2half2_rn(v.z, v.w);
        uint2 u; u.x = *(unsigned*)&h0; u.y = *(unsigned*)&h1;
        *(uint2*)(dst + i) = u;
    }
}

/* ---------------- edge-attr mean (deterministic 2-stage) ---------------- */
__global__ void k_eamean1(const float* __restrict__ ea) {
    const int SPAN = 1563;
    int blk = blockIdx.x;
    int w = threadIdx.x >> 5, lane = threadIdx.x & 31;
    long start = (long)blk * SPAN;
    long end = start + SPAN; if (end > NE) end = NE;
    float s = 0.f;
    for (long e = start + w; e < end; e += 4) s += ea[e * EFD + lane];
    __shared__ float sm[4][32];
    sm[w][lane] = s;
    __syncthreads();
    if (w == 0) {
        float t = sm[0][lane] + sm[1][lane] + sm[2][lane] + sm[3][lane];
        g_partial[blk * 32 + lane] = t;
    }
}
__global__ void k_eamean2() {
    int lane = threadIdx.x;
    float s = 0.f;
    for (int b = 0; b < 256; b++) s += g_partial[b * 32 + lane];
    g_eamean[lane] = s * (1.f / (float)NE);
}

/* ---------------- CSR build ---------------- */
__global__ void k_init_counts() {
    int i = blockIdx.x * blockDim.x + threadIdx.x;
    if (i < NN) g_counts[i] = 1;   /* self loop */
}
__global__ void k_count(const int* __restrict__ dst) {
    int e = blockIdx.x * blockDim.x + threadIdx.x;
    if (e < NE) atomicAdd(&g_counts[dst[e]], 1);
}
__global__ void k_scan_local() {
    __shared__ int sm[1024];
    int base = blockIdx.x * 1024;
    int t = threadIdx.x;
    int v = (base + t < NN) ? g_counts[base + t] : 0;
    sm[t] = v;
    __syncthreads();
    #pragma unroll
    for (int off = 1; off < 1024; off <<= 1) {
        int x = (t >= off) ? sm[t - off] : 0;
        __syncthreads();
        sm[t] += x;
        __syncthreads();
    }
    if (base + t < NN) g_rowptr[base + t] = sm[t] - v;   /* exclusive */
    if (t == 1023) g_bsums[blockIdx.x] = sm[1023];
}
__global__ void k_scan_fixup(int nb) {
    int lane = threadIdx.x;                 /* 32 threads; nb <= 32 */
    int v = (lane < nb) ? g_bsums[lane] : 0;
    int orig = v;
    #pragma unroll
    for (int off = 1; off < 32; off <<= 1) {
        int x = __shfl_up_sync(0xffffffffu, v, off);
        if (lane >= off) v += x;
    }
    if (lane < nb) g_bsums[lane] = v - orig;   /* exclusive */
    if (lane == 31) g_rowptr[NN] = v;          /* total */
}
__global__ void k_scan_add() {
    int i = blockIdx.x * blockDim.x + threadIdx.x;
    if (i < NN) {
        int r = g_rowptr[i] + g_bsums[i >> 10];
        g_rowptr[i] = r;
        g_fill[i] = r;
    }
}
__global__ void k_scatter_edges(const int* __restrict__ src, const int* __restrict__ dst) {
    int e = blockIdx.x * blockDim.x + threadIdx.x;
    if (e < NE) {
        int d = dst[e];
        int pos = atomicAdd(&g_fill[d], 1);
        g_csrsrc[pos] = src[e];
        g_csreid[pos] = e;
    }
}
__global__ void k_scatter_self() {
    int i = blockIdx.x * blockDim.x + threadIdx.x;
    if (i < NN) {
        int pos = atomicAdd(&g_fill[i], 1);
        g_csrsrc[pos] = i;
        g_csreid[pos] = NE + i;
    }
}

/* ================= tensor-core GEMM: C[M,N] = A[M,128] @ B[128,N] =========
   R13/R16-verified: fp16 pre-converted operands, BK=32 double buffer,
   STATIC 37.9KB smem, 2 blocks/SM, single-sync mainloop. Optional fused
   attention dots (av/dv); optional dual-output mode (C2). */

#define AS_H 5120      /* halves per A stage: 128*40 */
#define BS_H 4352      /* halves per B stage: 32*136 */
#define SMEM_BYTES 37888

template <typename OutT>
__global__ void __launch_bounds__(256, 2)
k_gemm_mma(const __half* __restrict__ A, const __half* __restrict__ B,
           OutT* __restrict__ C, int M, int N, const float* __restrict__ bias,
           const float* __restrict__ av, const float* __restrict__ dv,
           float* __restrict__ als_out, float* __restrict__ ald_out,
           OutT* __restrict__ C2) {
    __shared__ __align__(16) char smem[SMEM_BYTES];
    __half* As = (__half*)smem;                 /* [2][128][40] */
    __half* Bs = (__half*)(smem + 20480);       /* [2][32][136] */
    float*  Cs = (float*)smem;                  /* [128][72] epilogue reuse */

    const int tid = threadIdx.x;
    const int bm = blockIdx.y * 128;
    const int bn = C2 ? 0 : blockIdx.x * 128;
    if (C2 && blockIdx.x == 1) { B += 128 * 128; C = C2; }
    const int warp = tid >> 5;
    const int wm = warp >> 1;      /* 0..3 */
    const int wn = warp & 1;       /* 0..1 */

    const int r_a = tid >> 1, ca = (tid & 1) * 16;
    const int r_b = tid >> 3, cb = (tid & 7) * 16;
    const bool arow_ok = (bm + r_a) < M;
    const __half* Aptr = A + (long)(bm + r_a) * 128 + ca;
    const __half* Bptr = B + (long)r_b * N + bn + cb;

    uint4 pa0, pa1, pb0, pb1;
    #define LOAD_A(kk) do { \
        if (arow_ok) { \
            pa0 = *(const uint4*)(Aptr + (kk)); \
            pa1 = *(const uint4*)(Aptr + (kk) + 8); \
        } else { pa0 = make_uint4(0,0,0,0); pa1 = pa0; } \
    } while (0)
    #define LOAD_B(kk) do { \
        const __half* bp = Bptr + (long)(kk) * N; \
        pb0 = *(const uint4*)bp; \
        pb1 = *(const uint4*)(bp + 8); \
    } while (0)
    #define STS(st) do { \
        *(uint4*)(As + (st) * AS_H + r_a * 40 + ca) = pa0; \
        *(uint4*)(As + (st) * AS_H + r_a * 40 + ca + 8) = pa1; \
        *(uint4*)(Bs + (st) * BS_H + r_b * 136 + cb) = pb0; \
        *(uint4*)(Bs + (st) * BS_H + r_b * 136 + cb + 8) = pb1; \
    } while (0)

    wmma::fragment<wmma::accumulator, 16, 16, 16, float> cf[2][4];
    #pragma unroll
    for (int i = 0; i < 2; i++)
        #pragma unroll
        for (int j = 0; j < 4; j++) wmma::fill_fragment(cf[i][j], 0.f);

    LOAD_A(0); LOAD_B(0);
    STS(0);
    __syncthreads();

    #pragma unroll
    for (int t = 0; t < 4; t++) {
        if (t < 3) { LOAD_A((t + 1) * 32); LOAD_B((t + 1) * 32); }
        const int st = t & 1;
        #pragma unroll
        for (int ks = 0; ks < 2; ks++) {
            wmma::fragment<wmma::matrix_a, 16, 16, 16, __half, wmma::row_major> af0, af1;
            wmma::load_matrix_sync(af0, As + st * AS_H + (wm * 32) * 40 + ks * 16, 40);
            wmma::load_matrix_sync(af1, As + st * AS_H + (wm * 32 + 16) * 40 + ks * 16, 40);
            #pragma unroll
            for (int j = 0; j < 4; j++) {
                wmma::fragment<wmma::matrix_b, 16, 16, 16, __half, wmma::row_major> bf;
                wmma::load_matrix_sync(bf, Bs + st * BS_H + (ks * 16) * 136 + wn * 64 + j * 16, 136);
                wmma::mma_sync(cf[0][j], af0, bf, cf[0][j]);
                wmma::mma_sync(cf[1][j], af1, bf, cf[1][j]);
            }
        }
        if (t < 3) {
            STS((t + 1) & 1);
            __syncthreads();
        }
    }

    /* epilogue: two phases through smem (Cs reuses As/Bs) */
    const int r = tid >> 1;
    const int gm = bm + r;
    const int head = blockIdx.x;                     /* valid for N=512 x-GEMM */
    float ds = 0.f, dd = 0.f;

    #pragma unroll
    for (int ph = 0; ph < 2; ph++) {
        __syncthreads();
        #pragma unroll
        for (int i = 0; i < 2; i++)
            #pragma unroll
            for (int q = 0; q < 2; q++)
                wmma::store_matrix_sync(Cs + (wm * 32 + i * 16) * 72 + wn * 32 + q * 16,
                                        cf[i][ph * 2 + q], 72, wmma::mem_row_major);
        __syncthreads();
        int c0 = (tid & 1) * 32;
        if (gm < M) {
            const float* srow = Cs + r * 72 + c0;
            int colb = (c0 ? 64 : 0) + ph * 32;      /* column within 128 */
            int gnb = bn + colb;
            #pragma unroll
            for (int c = 0; c < 32; c += 4) {
                float4 v = *(const float4*)(srow + c);
                if (bias) {
                    v.x += bias[gnb + c + 0];
                    v.y += bias[gnb + c + 1];
                    v.z += bias[gnb + c + 2];
                    v.w += bias[gnb + c + 3];
                }
                if (av) {
                    float4 a4 = *(const float4*)(av + head * D + colb + c);
                    float4 b4 = *(const float4*)(dv + head * D + colb + c);
                    ds += v.x * a4.x + v.y * a4.y + v.z * a4.z + v.w * a4.w;
                    dd += v.x * b4.x + v.y * b4.y + v.z * b4.z + v.w * b4.w;
                }
                if (sizeof(OutT) == 4) {
                    *(float4*)((float*)C + (long)gm * N + gnb + c) = v;
                } else {
                    __half2 h0 = __floats2half2_rn(v.x, v.y);
                    __half2 h1 = __floats2half2_rn(v.z, v.w);
                    uint2 u; u.x = *(unsigned*)&h0; u.y = *(unsigned*)&h1;
                    *(uint2*)((__half*)C + (long)gm * N + gnb + c) = u;
                }
            }
        }
    }
    /* warp-uniform shuffle: executed by ALL lanes (av is uniform) */
    if (av) {
        ds += __shfl_xor_sync(0xffffffffu, ds, 1);
        dd += __shfl_xor_sync(0xffffffffu, dd, 1);
        if (gm < M && !(tid & 1)) {
            als_out[(long)gm * NH + head] = ds;
            ald_out[(long)gm * NH + head] = dd;
        }
    }
    #undef LOAD_A
    #undef LOAD_B
    #undef STS
}

/* ---------------- LayerNorm + FiLM (fp16 output; layer 0 only) ------------- */
__global__ void k_ln_film(const float* __restrict__ ls, const float* __restrict__ lb,
                          const float* __restrict__ gam, const float* __restrict__ bet) {
    int n = (blockIdx.x * blockDim.x + threadIdx.x) >> 5;
    int lane = threadIdx.x & 31;
    if (n >= NN) return;
    float4 v = *(const float4*)(g_h + n * D + lane * 4);
    float mu = wredsum(v.x + v.y + v.z + v.w) * (1.f / 128.f);
    float d0 = v.x - mu, d1 = v.y - mu, d2 = v.z - mu, d3 = v.w - mu;
    float var = wredsum(d0 * d0 + d1 * d1 + d2 * d2 + d3 * d3) * (1.f / 128.f);
    float rs = rsqrtf(var + 1e-5f);
    float4 lsv = *(const float4*)(ls + lane * 4);
    float4 lbv = *(const float4*)(lb + lane * 4);
    float4 gv = *(const float4*)(gam + lane * 4);
    float4 bv = *(const float4*)(bet + lane * 4);
    float o0 = gv.x * (d0 * rs * lsv.x + lbv.x) + bv.x;
    float o1 = gv.y * (d1 * rs * lsv.y + lbv.y) + bv.y;
    float o2 = gv.z * (d2 * rs * lsv.z + lbv.z) + bv.z;
    float o3 = gv.w * (d3 * rs * lsv.w + lbv.w) + bv.w;
    __half2 h0 = __floats2half2_rn(o0, o1);
    __half2 h1 = __floats2half2_rn(o2, o3);
    uint2 u; u.x = *(unsigned*)&h0; u.y = *(unsigned*)&h1;
    *(uint2*)(g_hm + n * D + lane * 4) = u;
}

/* ---------------- edge attention vectors: warp per output ---------------- */
__global__ void k_attvec(const float* __restrict__ gWe, const float* __restrict__ gaedge) {
    int gw = blockIdx.x * 8 + (threadIdx.x >> 5);   /* 0 .. NL*128-1 */
    int lane = threadIdx.x & 31;
    int l = gw >> 7;
    int o = gw & 127;
    int h = o >> 5, f = o & 31;
    const float* We = gWe + (long)l * EFD * NH * D + (long)f * (NH * D) + h * D;
    const float* ae = gaedge + (long)l * NH * D + h * D;
    float4 w4 = *(const float4*)(We + lane * 4);
    float4 a4 = *(const float4*)(ae + lane * 4);
    float s = wredsum(w4.x * a4.x + w4.y * a4.y + w4.z * a4.z + w4.w * a4.w);
    if (lane == 0) g_v[l * NH * EFD + h * EFD + f] = s;
}
__global__ void k_aleself() {
    int l = blockIdx.x;
    int h = threadIdx.x >> 5, lane = threadIdx.x & 31;
    float s = wredsum(g_eamean[lane] * g_v[l * NH * EFD + h * EFD + lane]);
    if (lane == 0) g_aleself[l * NH + h] = s;
}

/* ---------------- per-edge attention logit al_e for ALL layers -------------- */
__global__ void k_ale_all(const float* __restrict__ ea) {
    __shared__ float sv[NL * NH * EFD];   /* 768 floats */
    __shared__ float se[128 * 33];
    int t = threadIdx.x;           /* 128 */
    long base = (long)blockIdx.x * 128;
    for (int i = t; i < NL * NH * EFD; i += 128) sv[i] = g_v[i];
    #pragma unroll
    for (int i = 0; i < 32; i++) {
        long li = (long)t + (long)i * 128;
        long gi = base * EFD + li;
        if (gi < (long)NE * EFD) {
            int row = (int)(li >> 5), col = (int)(li & 31);
            se[row * 33 + col] = ea[gi];
        }
    }
    __syncthreads();
    long j = base + t;
    if (j >= NE) return;
    float ev[EFD];
    #pragma unroll
    for (int k = 0; k < EFD; k++) ev[k] = se[t * 33 + k];
    #pragma unroll
    for (int l = 0; l < NL; l++) {
        float s0 = 0.f, s1 = 0.f, s2 = 0.f, s3 = 0.f;
        const float* v = sv + l * NH * EFD;
        #pragma unroll
        for (int k = 0; k < EFD; k++) {
            float e = ev[k];
            s0 += e * v[k];
            s1 += e * v[EFD + k];
            s2 += e * v[2 * EFD + k];
            s3 += e * v[3 * EFD + k];
        }
        float* o = g_ale + ((long)l * NE + j) * NH;
        o[0] = s0; o[1] = s1; o[2] = s2; o[3] = s3;
    }
}

/* ---------------- fused attention: softmax + gather + NEXT-layer LN/FiLM ----
   If lnc != null (= {ls,lb,gam,bet} of the NEXT layer), the epilogue applies
   LN+FiLM in-register and writes g_hm (fp16). If o16 != null (last layer),
   writes raw h as fp16 to o16 instead. g_h fp32 is never written. */
__global__ void k_attn(const float* __restrict__ ale_l,
                       const float* __restrict__ aleself_l,
                       const float* __restrict__ bias,
                       const float* __restrict__ ls2, const float* __restrict__ lb2,
                       const float* __restrict__ gam2, const float* __restrict__ bet2,
                       __half* __restrict__ o16) {
    int n = (blockIdx.x * blockDim.x + threadIdx.x) >> 5;
    int lane = threadIdx.x & 31;
    if (n >= NN) return;
    int rb = g_rowptr[n], re = g_rowptr[n + 1];
    float4 ad = *(const float4*)(g_ald + (long)n * NH);

    float4 lw[4];
    int sreg[4];
    float4 mx = make_float4(-1e30f, -1e30f, -1e30f, -1e30f);
    #pragma unroll
    for (int j = 0; j < 4; j++) {
        int i = rb + lane + j * 32;
        lw[j] = make_float4(-1e30f, -1e30f, -1e30f, -1e30f);
        sreg[j] = 0;
        if (i < re) {
            int s = g_csrsrc[i], e = g_csreid[i];
            sreg[j] = s;
            float4 as = *(const float4*)(g_als + (long)s * NH);
            float4 ae = (e < NE) ? *(const float4*)(ale_l + (long)e * NH)
                                 : *(const float4*)aleself_l;
            float4 a; float t;
            t = as.x + ad.x + ae.x; a.x = t > 0.f ? t : 0.2f * t;
            t = as.y + ad.y + ae.y; a.y = t > 0.f ? t : 0.2f * t;
            t = as.z + ad.z + ae.z; a.z = t > 0.f ? t : 0.2f * t;
            t = as.w + ad.w + ae.w; a.w = t > 0.f ? t : 0.2f * t;
            lw[j] = a;
            mx.x = fmaxf(mx.x, a.x); mx.y = fmaxf(mx.y, a.y);
            mx.z = fmaxf(mx.z, a.z); mx.w = fmaxf(mx.w, a.w);
        }
    }
    for (int i = rb + lane + 128; i < re; i += 32) {   /* rare deg>128 spill */
        int s = g_csrsrc[i], e = g_csreid[i];
        float4 as = *(const float4*)(g_als + (long)s * NH);
        float4 ae = (e < NE) ? *(const float4*)(ale_l + (long)e * NH)
                             : *(const float4*)aleself_l;
        float4 a; float t;
        t = as.x + ad.x + ae.x; a.x = t > 0.f ? t : 0.2f * t;
        t = as.y + ad.y + ae.y; a.y = t > 0.f ? t : 0.2f * t;
        t = as.z + ad.z + ae.z; a.z = t > 0.f ? t : 0.2f * t;
        t = as.w + ad.w + ae.w; a.w = t > 0.f ? t : 0.2f * t;
        *(float4*)(g_lg + (long)i * NH) = a;
        mx.x = fmaxf(mx.x, a.x); mx.y = fmaxf(mx.y, a.y);
        mx.z = fmaxf(mx.z, a.z); mx.w = fmaxf(mx.w, a.w);
    }
    wredmax4(mx);

    float4 den = make_float4(0.f, 0.f, 0.f, 0.f);
    #pragma unroll
    for (int j = 0; j < 4; j++) {
        bool valid = (rb + lane + j * 32) < re;
        float4 a = lw[j];
        a.x = valid ? __expf(a.x - mx.x) : 0.f;
        a.y = valid ? __expf(a.y - mx.y) : 0.f;
        a.z = valid ? __expf(a.z - mx.z) : 0.f;
        a.w = valid ? __expf(a.w - mx.w) : 0.f;
        lw[j] = a;
        den.x += a.x; den.y += a.y; den.z += a.z; den.w += a.w;
    }
    for (int i = rb + lane + 128; i < re; i += 32) {
        float4 a = *(const float4*)(g_lg + (long)i * NH);
        a.x = __expf(a.x - mx.x); a.y = __expf(a.y - mx.y);
        a.z = __expf(a.z - mx.z); a.w = __expf(a.w - mx.w);
        *(float4*)(g_lg + (long)i * NH) = a;
        den.x += a.x; den.y += a.y; den.z += a.z; den.w += a.w;
    }
    wredsum4(den);
    float4 scl;
    scl.x = 0.25f / (den.x + 1e-16f);
    scl.y = 0.25f / (den.y + 1e-16f);
    scl.z = 0.25f / (den.z + 1e-16f);
    scl.w = 0.25f / (den.w + 1e-16f);

    #pragma unroll
    for (int j = 0; j < 4; j++) {
        int i = rb + lane + j * 32;
        if (i < re) {
            float4 o;
            o.x = lw[j].x * scl.x; o.y = lw[j].y * scl.y;
            o.z = lw[j].z * scl.z; o.w = lw[j].w * scl.w;
            *(float4*)(g_lg + (long)i * NH) = o;
        }
    }
    for (int i = rb + lane + 128; i < re; i += 32) {
        float4 a = *(const float4*)(g_lg + (long)i * NH);
        a.x *= scl.x; a.y *= scl.y; a.z *= scl.z; a.w *= scl.w;
        *(float4*)(g_lg + (long)i * NH) = a;
    }

    __syncwarp();   /* order g_lg writes before same-warp reads below */

    /* ---- pass B: weighted gather ---- */
    const int hh = lane >> 3;
    const int dp = (lane & 7) << 4;
    float acc[16];
    #pragma unroll
    for (int k = 0; k < 16; k++) acc[k] = 0.f;

    for (int i = rb; i < re; i++) {
        int rel = i - rb;
        int s;
        if (rel < 128) {
            int slot = rel >> 5;
            s = __shfl_sync(0xffffffffu, slot == 0 ? sreg[0] :
                            slot == 1 ? sreg[1] : slot == 2 ? sreg[2] : sreg[3],
                            rel & 31);
        } else {
            s = g_csrsrc[i];
        }
        float w = g_lg[(long)i * NH + hh];
        const __half* xp = g_x + (((long)s * NH + hh) << 7) + dp;
        uint4 r0 = *(const uint4*)xp;
        uint4 r1 = *(const uint4*)(xp + 8);
        const __half2* hp0 = (const __half2*)&r0;
        const __half2* hp1 = (const __half2*)&r1;
        #pragma unroll
        for (int q = 0; q < 4; q++) {
            float2 f = __half22float2(hp0[q]);
            acc[q * 2 + 0] += w * f.x;
            acc[q * 2 + 1] += w * f.y;
        }
        #pragma unroll
        for (int q = 0; q < 4; q++) {
            float2 f = __half22float2(hp1[q]);
            acc[8 + q * 2 + 0] += w * f.x;
            acc[8 + q * 2 + 1] += w * f.y;
        }
    }
    #pragma unroll
    for (int k = 0; k < 16; k++) {
        float vv = acc[k];
        vv += __shfl_xor_sync(0xffffffffu, vv, 8);
        vv += __shfl_xor_sync(0xffffffffu, vv, 16);
        acc[k] = vv;
    }

    /* final h (bias + ReLU) — every lane holds a full copy of its 16 dims */
    float ov[16];
    float s1 = 0.f, s2 = 0.f;
    #pragma unroll
    for (int k = 0; k < 16; k++) {
        float o = fmaxf(acc[k] + bias[dp + k], 0.f);
        ov[k] = o;
        s1 += o;
        s2 += o * o;
    }

    if (ls2) {      /* fused NEXT-layer LN+FiLM (uniform branch) */
        /* warp holds 4 redundant copies of the 128 dims -> divide by 4 */
        float mu = wredsum(s1) * (0.25f / 128.f);
        float ssq = wredsum(s2) * (0.25f / 128.f);
        float var = ssq - mu * mu;
        float rs = rsqrtf(var + 1e-5f);
        if (lane < 8) {
            __half2 hh2[8];
            #pragma unroll
            for (int k = 0; k < 4; k++) {
                float4 lsv = *(const float4*)(ls2 + dp + k * 4);
                float4 lbv = *(const float4*)(lb2 + dp + k * 4);
                float4 gv  = *(const float4*)(gam2 + dp + k * 4);
                float4 bv  = *(const float4*)(bet2 + dp + k * 4);
                float m0 = gv.x * ((ov[k*4+0] - mu) * rs * lsv.x + lbv.x) + bv.x;
                float m1 = gv.y * ((ov[k*4+1] - mu) * rs * lsv.y + lbv.y) + bv.y;
                float m2 = gv.z * ((ov[k*4+2] - mu) * rs * lsv.z + lbv.z) + bv.z;
                float m3 = gv.w * ((ov[k*4+3] - mu) * rs * lsv.w + lbv.w) + bv.w;
                hh2[k*2+0] = __floats2half2_rn(m0, m1);
                hh2[k*2+1] = __floats2half2_rn(m2, m3);
            }
            *(uint4*)(g_hm + n * D + dp)     = *(const uint4*)&hh2[0];
            *(uint4*)(g_hm + n * D + dp + 8) = *(const uint4*)&hh2[4];
        }
    } else {        /* last layer: raw h fp16 for the head GEMM */
        if (lane < 8) {
            __half2 hh2[8];
            #pragma unroll
            for (int q = 0; q < 8; q++)
                hh2[q] = __floats2half2_rn(ov[q * 2], ov[q * 2 + 1]);
            *(uint4*)(o16 + n * D + dp)     = *(const uint4*)&hh2[0];
            *(uint4*)(o16 + n * D + dp + 8) = *(const uint4*)&hh2[4];
        }
    }
}

/* ---------------- fused edge head ---------------- */
__global__ void __launch_bounds__(256)
k_edge_head(const int* __restrict__ src, const int* __restrict__ dst,
            const float* __restrict__ W1, const float* __restrict__ b1,
            const float* __restrict__ W2, const float* __restrict__ b2,
            const float* __restrict__ ea, float* __restrict__ out) {
    __shared__ float sW[EFD][128];
    __shared__ float sb[128], sw2[128];
    int tid = threadIdx.x;
    for (int i = tid; i < EFD * 128; i += 256) sW[i >> 7][i & 127] = W1[256 * 128 + i];
    if (tid < 128) { sb[tid] = b1[tid]; sw2[tid] = W2[tid]; }
    __syncthreads();
    float bias2 = b2[0];
    int lane = tid & 31;
    int warp = blockIdx.x * 8 + (tid >> 5);
    int nwarps = gridDim.x * 8;
    const int NG = NE / 4;
    for (int g = warp; g < NG; g += nwarps) {
        int e = g * 4;
        float ev[4];
        float4 tu[4];
        #pragma unroll
        for (int k = 0; k < 4; k++) {
            int s = src[e + k], d = dst[e + k];
            ev[k] = ea[(long)(e + k) * EFD + lane];
            float4 tv = *(const float4*)(g_t + (long)s * D + lane * 4);
            float4 uv = *(const float4*)(g_u + (long)d * D + lane * 4);
            tu[k].x = tv.x + uv.x; tu[k].y = tv.y + uv.y;
            tu[k].z = tv.z + uv.z; tu[k].w = tv.w + uv.w;
        }
        float4 p[4];
        #pragma unroll
        for (int k = 0; k < 4; k++) p[k] = make_float4(0.f, 0.f, 0.f, 0.f);
        #pragma unroll
        for (int j = 0; j < EFD; j++) {
            float4 w = *(const float4*)&sW[j][lane * 4];
            #pragma unroll
            for (int k = 0; k < 4; k++) {
                float bj = __shfl_sync(0xffffffffu, ev[k], j);
                p[k].x += bj * w.x; p[k].y += bj * w.y;
                p[k].z += bj * w.z; p[k].w += bj * w.w;
            }
        }
        float4 bb = *(const float4*)&sb[lane * 4];
        float4 w2 = *(const float4*)&sw2[lane * 4];
        #pragma unroll
        for (int k = 0; k < 4; k++) {
            float z0 = fmaxf(tu[k].x + p[k].x + bb.x, 0.f);
            float z1 = fmaxf(tu[k].y + p[k].y + bb.y, 0.f);
            float z2 = fmaxf(tu[k].z + p[k].z + bb.z, 0.f);
            float z3 = fmaxf(tu[k].w + p[k].w + bb.w, 0.f);
            float s4 = wredsum(z0 * w2.x + z1 * w2.y + z2 * w2.z + z3 * w2.w);
            if (lane == 0) out[e + k] = s4 + bias2;
        }
    }
}

/* ---------------- host orchestration ---------------- */
extern "C" void kernel_launch(void* const* d_in, const int* in_sizes, int n_in,
                              void* d_out, int out_size) {
    const float* x      = (const float*)d_in[0];
    const int*   ei     = (const int*)  d_in[1];
    const float* ea     = (const float*)d_in[2];
    const float* gamma  = (const float*)d_in[3];
    const float* beta   = (const float*)d_in[4];
    const float* embW   = (const float*)d_in[5];
    const float* embb   = (const float*)d_in[6];
    const float* lns    = (const float*)d_in[7];
    const float* lnb    = (const float*)d_in[8];
    const float* gatW   = (const float*)d_in[9];
    const float* asrc   = (const float*)d_in[10];
    const float* adst   = (const float*)d_in[11];
    const float* gWe    = (const float*)d_in[12];
    const float* aedge  = (const float*)d_in[13];
    const float* gbias  = (const float*)d_in[14];
    const float* W1     = (const float*)d_in[15];
    const float* b1     = (const float*)d_in[16];
    const float* W2     = (const float*)d_in[17];
    const float* b2     = (const float*)d_in[18];
    float* out = (float*)d_out;

    const int* src = ei;
    const int* dst = ei + NE;

    float *p_h, *p_t, *p_u, *p_ale, *p_aleself, *p_als, *p_ald;
    __half *p_x, *p_hm, *p_xh, *p_wh, *p_ewh, *p_w1h;
    cudaGetSymbolAddress((void**)&p_h,  g_h);
    cudaGetSymbolAddress((void**)&p_hm, g_hm);
    cudaGetSymbolAddress((void**)&p_x,  g_x);
    cudaGetSymbolAddress((void**)&p_xh, g_xh);
    cudaGetSymbolAddress((void**)&p_wh, g_wh);
    cudaGetSymbolAddress((void**)&p_ewh, g_ewh);
    cudaGetSymbolAddress((void**)&p_w1h, g_w1h);
    cudaGetSymbolAddress((void**)&p_t,  g_t);
    cudaGetSymbolAddress((void**)&p_u,  g_u);
    cudaGetSymbolAddress((void**)&p_ale, g_ale);
    cudaGetSymbolAddress((void**)&p_aleself, g_aleself);
    cudaGetSymbolAddress((void**)&p_als, g_als);
    cudaGetSymbolAddress((void**)&p_ald, g_ald);

    const int MB = (NN + 127) / 128;   /* 196 */

    /* fp16 pre-conversions */
    k_f2h<<<(NN * D / 4 + 255) / 256, 256>>>(x, p_xh, NN * D);
    k_f2h<<<(D * D / 4 + 255) / 256, 256>>>(embW, p_ewh, D * D);
    k_f2h<<<(NL * D * NH * D / 4 + 255) / 256, 256>>>(gatW, p_wh, NL * D * NH * D);

    /* embed GEMM -> g_h (fp32), then layer-0 LN/FiLM -> g_hm */
    k_gemm_mma<float><<<dim3(1, MB), 256>>>(p_xh, p_ewh, p_h, NN, 128, embb,
                                            (const float*)0, (const float*)0,
                                            (float*)0, (float*)0, (float*)0);

    k_f2h<<<(2 * D * D / 4 + 255) / 256, 256>>>(W1, p_w1h, 2 * D * D);

    /* CSR build */
    k_init_counts<<<(NN + 255) / 256, 256>>>();
    k_count<<<(NE + 255) / 256, 256>>>(dst);
    int nb = (NN + 1023) / 1024;
    k_scan_local<<<nb, 1024>>>();
    k_scan_fixup<<<1, 32>>>(nb);
    k_scan_add<<<(NN + 255) / 256, 256>>>();
    k_scatter_edges<<<(NE + 255) / 256, 256>>>(src, dst);
    k_scatter_self<<<(NN + 255) / 256, 256>>>();

    /* constants */
    k_eamean1<<<256, 128>>>(ea);
    k_eamean2<<<1, 32>>>();
    k_attvec<<<NL * 16, 256>>>(gWe, aedge);
    k_aleself<<<NL, 128>>>();
    k_ale_all<<<(NE + 127) / 128, 128>>>(ea);

    /* layer-0 LN/FiLM (only remaining standalone LN) */
    k_ln_film<<<(NN * 32 + 255) / 256, 256>>>(lns, lnb, gamma, beta);

    /* layers: GEMM then attn (attn fuses NEXT layer's LN, or emits fp16 h) */
    for (int l = 0; l < NL; l++) {
        k_gemm_mma<__half><<<dim3(4, MB), 256>>>(p_hm, p_wh + (long)l * D * NH * D,
                                                 p_x, NN, 512, (const float*)0,
                                                 asrc + l * NH * D, adst + l * NH * D,
                                                 p_als, p_ald, (__half*)0);
        if (l < NL - 1) {
            k_attn<<<(NN * 32 + 255) / 256, 256>>>(p_ale + (long)l * NE * NH,
                                                   p_aleself + l * NH,
                                                   gbias + l * D,
                                                   lns + (l + 1) * D, lnb + (l + 1) * D,
                                                   gamma + (l + 1) * D, beta + (l + 1) * D,
                                                   (__half*)0);
        } else {
            k_attn<<<(NN * 32 + 255) / 256, 256>>>(p_ale + (long)l * NE * NH,
                                                   p_aleself + l * NH,
                                                   gbias + l * D,
                                                   (const float*)0, (const float*)0,
                                                   (const float*)0, (const float*)0,
                                                   p_xh);
        }
    }

    /* head: dual-output GEMM (t and u in one launch), fused edge head */
    k_gemm_mma<float><<<dim3(2, MB), 256>>>(p_xh, p_w1h, p_t, NN, 128, (const float*)0,
                                            (const float*)0, (const float*)0,
                                            (float*)0, (float*)0, p_u);
    k_edge_head<<<2048, 256>>>(src, dst, W1, b1, W2, b2, ea, out);
}